// round 1
// baseline (speedup 1.0000x reference)
#include <cuda_runtime.h>
#include <cuda_bf16.h>
#include <cstdint>

// Problem shape (fixed by the dataset)
#define B 4
#define N 4096
#define D 256
#define NW (N / 64)          // 64 bit-words per row
#define SIM_THR 0.7f

// ---------------- device scratch (zero-initialized at module load) ----------
__device__ float              g_sorted[(size_t)B * N * D];   // normalized tokens, sorted by score desc
__device__ int                g_order[B * N];                // order[r] = original index of rank r
__device__ unsigned long long g_bits[(size_t)B * N * NW];    // suppression bits (j > i only)
__device__ float              g_keep[B * N];                 // keep mask in ORIGINAL token order

// ---------------- 1. rank by counting (stable argsort of -scores) ----------
__global__ void rank_kernel(const float* __restrict__ scores) {
    __shared__ float s[N];
    const int b   = blockIdx.x;
    const int tid = threadIdx.x;                 // 1024 threads
    const float* sc = scores + b * N;
    #pragma unroll
    for (int t = 0; t < 4; t++) s[tid + t * 1024] = sc[tid + t * 1024];
    __syncthreads();

    int   idx[4];
    float si[4];
    int   rank[4];
    #pragma unroll
    for (int t = 0; t < 4; t++) {
        idx[t]  = tid + t * 1024;
        si[t]   = s[idx[t]];
        rank[t] = 0;
    }
    for (int j = 0; j < N; j++) {
        const float sj = s[j];
        #pragma unroll
        for (int t = 0; t < 4; t++)
            rank[t] += (sj > si[t]) || (sj == si[t] && j < idx[t]);
    }
    #pragma unroll
    for (int t = 0; t < 4; t++)
        g_order[b * N + rank[t]] = idx[t];
}

// ---------------- 2. normalize + gather into sorted order ------------------
__global__ void norm_gather_kernel(const float* __restrict__ tokens) {
    const int gw   = (blockIdx.x * blockDim.x + threadIdx.x) >> 5;  // one warp per sorted row
    const int lane = threadIdx.x & 31;
    if (gw >= B * N) return;
    const int src_i = g_order[gw];
    const int b     = gw / N;
    const float* src = tokens + ((size_t)b * N + src_i) * D;
    float4 v0 = *(const float4*)(src + lane * 8);
    float4 v1 = *(const float4*)(src + lane * 8 + 4);
    float ss = v0.x*v0.x + v0.y*v0.y + v0.z*v0.z + v0.w*v0.w
             + v1.x*v1.x + v1.y*v1.y + v1.z*v1.z + v1.w*v1.w;
    #pragma unroll
    for (int o = 16; o > 0; o >>= 1) ss += __shfl_xor_sync(0xffffffffu, ss, o);
    const float inv = 1.0f / (sqrtf(ss) + 1e-6f);
    float* dst = g_sorted + (size_t)gw * D;
    v0.x*=inv; v0.y*=inv; v0.z*=inv; v0.w*=inv;
    v1.x*=inv; v1.y*=inv; v1.z*=inv; v1.w*=inv;
    *(float4*)(dst + lane * 8)     = v0;
    *(float4*)(dst + lane * 8 + 4) = v1;
}

// ---------------- 3. similarity tiles -> suppression bits -------------------
// 64x64 output tile per block, 256 threads, 4x4 microtile, K-chunks of 32.
// Only upper-triangle tiles (tj >= ti). Lower-triangle bit-words are never
// written and stay zero from static init (replay-safe: every written word is
// fully overwritten each launch).
__global__ void __launch_bounds__(256, 4) sim_bits_kernel() {
    const int tj = blockIdx.x;       // column tile == bit-word index
    const int ti = blockIdx.y;       // row tile
    const int b  = blockIdx.z;
    if (tj < ti) return;

    __shared__ float As[32][68];     // k-major, 68*4B=272B row stride (16B aligned)
    __shared__ float Bs[32][68];
    __shared__ unsigned long long sbits[64];

    const int tid = threadIdx.x;
    const int tx  = tid & 15;        // 16 col-threads
    const int ty  = tid >> 4;        // 16 row-threads

    const float* Abase = g_sorted + ((size_t)b * N + ti * 64) * D;
    const float* Bbase = g_sorted + ((size_t)b * N + tj * 64) * D;

    float acc[4][4] = {};

    for (int kc = 0; kc < D; kc += 32) {
        #pragma unroll
        for (int l = 0; l < 2; l++) {
            const int e   = tid + l * 256;
            const int row = e >> 3;
            const int k4  = (e & 7) * 4;
            float4 va = *(const float4*)(Abase + row * D + kc + k4);
            As[k4+0][row] = va.x; As[k4+1][row] = va.y;
            As[k4+2][row] = va.z; As[k4+3][row] = va.w;
            float4 vb = *(const float4*)(Bbase + row * D + kc + k4);
            Bs[k4+0][row] = vb.x; Bs[k4+1][row] = vb.y;
            Bs[k4+2][row] = vb.z; Bs[k4+3][row] = vb.w;
        }
        __syncthreads();
        #pragma unroll
        for (int kk = 0; kk < 32; kk++) {
            const float4 a  = *(const float4*)&As[kk][ty * 4];
            const float4 bb = *(const float4*)&Bs[kk][tx * 4];
            const float ar[4] = {a.x, a.y, a.z, a.w};
            const float br[4] = {bb.x, bb.y, bb.z, bb.w};
            #pragma unroll
            for (int i = 0; i < 4; i++)
                #pragma unroll
                for (int j = 0; j < 4; j++)
                    acc[i][j] += ar[i] * br[j];
        }
        __syncthreads();
    }

    if (tid < 64) sbits[tid] = 0ull;
    __syncthreads();

    #pragma unroll
    for (int i = 0; i < 4; i++) {
        const int row = ty * 4 + i;
        const int gi  = ti * 64 + row;
        unsigned long long m = 0ull;
        #pragma unroll
        for (int j = 0; j < 4; j++) {
            const int col = tx * 4 + j;
            const int gj  = tj * 64 + col;
            if (acc[i][j] > SIM_THR && gj > gi) m |= 1ull << col;
        }
        if (m) atomicOr(&sbits[row], m);
    }
    __syncthreads();

    if (tid < 64)
        g_bits[((size_t)(b * N + ti * 64 + tid)) * NW + tj] = sbits[tid];
}

// ---------------- 4. sequential greedy scan over the bit matrix -------------
// One warp per batch. Suppressed mask = 64 words, 2 per lane (lane, lane+32).
__global__ void scan_kernel() {
    const int b    = blockIdx.x;
    const int lane = threadIdx.x;
    const unsigned long long* rows = g_bits + (size_t)b * N * NW;
    const int*   order = g_order + b * N;
    float*       keepf = g_keep  + b * N;

    unsigned long long sup0 = 0ull, sup1 = 0ull;
    unsigned long long r0 = rows[lane], r1 = rows[lane + 32];
    int ord = order[0];

    for (int i = 0; i < N; i++) {
        // prefetch next row (independent of keep decision)
        unsigned long long n0 = 0ull, n1 = 0ull;
        int nord = 0;
        if (i + 1 < N) {
            n0 = rows[(size_t)(i + 1) * NW + lane];
            n1 = rows[(size_t)(i + 1) * NW + lane + 32];
            nord = order[i + 1];
        }
        const int w = i >> 6;
        const unsigned long long sel = (w >= 32) ? sup1 : sup0;
        const unsigned long long sw  = __shfl_sync(0xffffffffu, sel, w & 31);
        const bool keep = ((sw >> (i & 63)) & 1ull) == 0ull;
        if (lane == 0) keepf[ord] = keep ? 1.0f : 0.0f;
        const unsigned long long m = keep ? ~0ull : 0ull;
        sup0 |= r0 & m;
        sup1 |= r1 & m;
        r0 = n0; r1 = n1; ord = nord;
    }
}

// ---------------- 5. outputs -------------------------------------------------
__global__ void mask_kernel(const float4* __restrict__ tok, float4* __restrict__ out) {
    const int idx = blockIdx.x * blockDim.x + threadIdx.x;   // float4 index
    if (idx >= B * N * (D / 4)) return;
    const float k = g_keep[idx >> 6];                        // D/4 = 64 float4 per token
    float4 v = tok[idx];
    v.x *= k; v.y *= k; v.z *= k; v.w *= k;
    out[idx] = v;
}

__global__ void keep_out_kernel(float* __restrict__ out, int count) {
    const int t = blockIdx.x * blockDim.x + threadIdx.x;
    if (t < count) out[t] = g_keep[t];
}

// ---------------- launch -----------------------------------------------------
extern "C" void kernel_launch(void* const* d_in, const int* in_sizes, int n_in,
                              void* d_out, int out_size) {
    const float* tokens = (const float*)d_in[0];
    const float* scores = (const float*)d_in[1];
    float* out = (float*)d_out;

    rank_kernel<<<B, 1024>>>(scores);

    {
        const int warps  = B * N;
        const int thr    = 256;
        const int blocks = (warps * 32 + thr - 1) / thr;
        norm_gather_kernel<<<blocks, thr>>>(tokens);
    }

    {
        dim3 grid(NW, NW, B);   // 64 x 64 x 4, lower-triangle blocks early-exit
        sim_bits_kernel<<<grid, 256>>>();
    }

    scan_kernel<<<B, 32>>>();

    {
        const int total4 = B * N * (D / 4);
        mask_kernel<<<(total4 + 255) / 256, 256>>>((const float4*)tokens, (float4*)out);
    }

    const long long bnd = (long long)B * N * D;
    if ((long long)out_size > bnd) {
        int extra = (int)((long long)out_size - bnd);
        if (extra > B * N) extra = B * N;
        keep_out_kernel<<<(extra + 255) / 256, 256>>>(out + bnd, extra);
    }
}

// round 2
// speedup vs baseline: 2.5639x; 2.5639x over previous
#include <cuda_runtime.h>
#include <cuda_bf16.h>
#include <cstdint>

#define B 4
#define N 4096
#define D 256
#define NW (N / 64)
#define SIM_THR 0.7f
#define LDK 136              // smem row stride in bf16 (128 + 8 pad -> conflict-free ldmatrix)

// ---------------- device scratch (zero-initialized at module load) ----------
__device__ __nv_bfloat16     g_sorted[(size_t)B * N * D];   // normalized, sorted by score desc
__device__ int               g_order[B * N];
__device__ unsigned long long g_bits[(size_t)B * N * NW];   // suppression bits (j > i only)
__device__ float             g_keep[B * N];

// ---------------- 1. rank by counting (stable argsort of -scores) ----------
__global__ void rank_kernel(const float* __restrict__ scores) {
    __shared__ float s[N];
    const int b     = blockIdx.x;
    const int chunk = blockIdx.y;            // 4 chunks of 1024 tokens
    const int tid   = threadIdx.x;           // 1024 threads
    const float* sc = scores + b * N;
    #pragma unroll
    for (int t = 0; t < 4; t++) s[tid + t * 1024] = sc[tid + t * 1024];
    __syncthreads();

    const int   idx = chunk * 1024 + tid;
    const float si  = s[idx];
    int rank = 0;
    for (int j = 0; j < N; j++) {
        const float sj = s[j];
        rank += (sj > si) || (sj == si && j < idx);
    }
    g_order[b * N + rank] = idx;
}

// ---------------- 2. normalize + gather into sorted order (fp32 -> bf16) ----
__device__ inline unsigned pack_bf2(float a, float b) {
    __nv_bfloat162 h = __floats2bfloat162_rn(a, b);
    return *reinterpret_cast<unsigned*>(&h);
}

__global__ void norm_gather_kernel(const float* __restrict__ tokens) {
    const int gw   = (blockIdx.x * blockDim.x + threadIdx.x) >> 5;
    const int lane = threadIdx.x & 31;
    if (gw >= B * N) return;
    const int src_i = g_order[gw];
    const int b     = gw / N;
    const float* src = tokens + ((size_t)b * N + src_i) * D;
    float4 v0 = *(const float4*)(src + lane * 8);
    float4 v1 = *(const float4*)(src + lane * 8 + 4);
    float ss = v0.x*v0.x + v0.y*v0.y + v0.z*v0.z + v0.w*v0.w
             + v1.x*v1.x + v1.y*v1.y + v1.z*v1.z + v1.w*v1.w;
    #pragma unroll
    for (int o = 16; o > 0; o >>= 1) ss += __shfl_xor_sync(0xffffffffu, ss, o);
    const float inv = 1.0f / (sqrtf(ss) + 1e-6f);
    uint4 u;
    u.x = pack_bf2(v0.x * inv, v0.y * inv);
    u.y = pack_bf2(v0.z * inv, v0.w * inv);
    u.z = pack_bf2(v1.x * inv, v1.y * inv);
    u.w = pack_bf2(v1.z * inv, v1.w * inv);
    *(uint4*)(g_sorted + (size_t)gw * D + lane * 8) = u;
}

// ---------------- 3. bf16 tensor-core similarity -> suppression bits --------
// 64x64 tile per block, 8 warps (4 m x 2 n), each warp m16 x n32 via
// mma.sync.m16n8k16. K chunked at 128 (2 chunks). Lower-triangle bit-words
// stay zero from static init; every written word is fully overwritten.
__global__ void __launch_bounds__(256) sim_bits_kernel() {
    const int tj = blockIdx.x;
    const int ti = blockIdx.y;
    const int b  = blockIdx.z;
    if (tj < ti) return;

    __shared__ __nv_bfloat16 As[64 * LDK];
    __shared__ __nv_bfloat16 Bs[64 * LDK];
    __shared__ unsigned long long sbits[64];

    const int tid  = threadIdx.x;
    const int lane = tid & 31;
    const int w    = tid >> 5;
    const int wm   = w & 3;          // m-tile: rows wm*16 .. +15
    const int wn   = w >> 2;         // n-half: cols wn*32 .. +31

    const __nv_bfloat16* Ab = g_sorted + ((size_t)b * N + ti * 64) * D;
    const __nv_bfloat16* Bb = g_sorted + ((size_t)b * N + tj * 64) * D;

    if (tid < 64) sbits[tid] = 0ull;

    float acc[4][4] = {};            // 4 n-subtiles x 4 c-regs

    // ldmatrix element offsets (within current k-chunk)
    const uint32_t a_off = (uint32_t)((wm * 16 + (lane & 15)) * LDK + (lane >> 4) * 8);
    const uint32_t b_row_base = (uint32_t)(wn * 32 + (lane & 7) + ((lane >> 4) << 3));
    const uint32_t b_col = (uint32_t)(((lane >> 3) & 1) * 8);

    const uint32_t As_base = (uint32_t)__cvta_generic_to_shared(As);
    const uint32_t Bs_base = (uint32_t)__cvta_generic_to_shared(Bs);

    for (int kc = 0; kc < D; kc += 128) {
        // load 64 x 128 bf16 for A and B: 1024 16B-chunks each, 4 per thread
        #pragma unroll
        for (int l = 0; l < 4; l++) {
            const int e   = tid + l * 256;
            const int row = e >> 4;
            const int c8  = (e & 15) * 8;
            *(uint4*)(As + row * LDK + c8) = *(const uint4*)(Ab + row * D + kc + c8);
            *(uint4*)(Bs + row * LDK + c8) = *(const uint4*)(Bb + row * D + kc + c8);
        }
        __syncthreads();

        #pragma unroll
        for (int ks = 0; ks < 8; ks++) {
            uint32_t a0, a1, a2, a3;
            {
                const uint32_t addr = As_base + (a_off + ks * 16) * 2;
                asm volatile("ldmatrix.sync.aligned.m8n8.x4.shared.b16 {%0,%1,%2,%3}, [%4];\n"
                             : "=r"(a0), "=r"(a1), "=r"(a2), "=r"(a3) : "r"(addr));
            }
            #pragma unroll
            for (int p = 0; p < 2; p++) {
                uint32_t b0, b1, b2, b3;
                const uint32_t addr = Bs_base +
                    ((b_row_base + p * 16) * LDK + ks * 16 + b_col) * 2;
                asm volatile("ldmatrix.sync.aligned.m8n8.x4.shared.b16 {%0,%1,%2,%3}, [%4];\n"
                             : "=r"(b0), "=r"(b1), "=r"(b2), "=r"(b3) : "r"(addr));
                asm volatile("mma.sync.aligned.m16n8k16.row.col.f32.bf16.bf16.f32 "
                             "{%0,%1,%2,%3}, {%4,%5,%6,%7}, {%8,%9}, {%0,%1,%2,%3};\n"
                             : "+f"(acc[p*2][0]), "+f"(acc[p*2][1]),
                               "+f"(acc[p*2][2]), "+f"(acc[p*2][3])
                             : "r"(a0), "r"(a1), "r"(a2), "r"(a3), "r"(b0), "r"(b1));
                asm volatile("mma.sync.aligned.m16n8k16.row.col.f32.bf16.bf16.f32 "
                             "{%0,%1,%2,%3}, {%4,%5,%6,%7}, {%8,%9}, {%0,%1,%2,%3};\n"
                             : "+f"(acc[p*2+1][0]), "+f"(acc[p*2+1][1]),
                               "+f"(acc[p*2+1][2]), "+f"(acc[p*2+1][3])
                             : "r"(a0), "r"(a1), "r"(a2), "r"(a3), "r"(b2), "r"(b3));
            }
        }
        __syncthreads();
    }

    // epilogue: threshold -> bits. c-frag: rows t/4 and t/4+8; cols 2*(t%4)+{0,1}
    const int r0 = wm * 16 + (lane >> 2);
    const int r1 = r0 + 8;
    const int gi0 = ti * 64 + r0;
    const int gi1 = ti * 64 + r1;
    unsigned long long m0 = 0ull, m1 = 0ull;
    #pragma unroll
    for (int nt = 0; nt < 4; nt++) {
        const int cb = wn * 32 + nt * 8 + ((lane & 3) << 1);  // local col in 0..63
        const int gj = tj * 64 + cb;
        if (acc[nt][0] > SIM_THR && gj     > gi0) m0 |= 1ull << cb;
        if (acc[nt][1] > SIM_THR && gj + 1 > gi0) m0 |= 1ull << (cb + 1);
        if (acc[nt][2] > SIM_THR && gj     > gi1) m1 |= 1ull << cb;
        if (acc[nt][3] > SIM_THR && gj + 1 > gi1) m1 |= 1ull << (cb + 1);
    }
    if (m0) atomicOr(&sbits[r0], m0);
    if (m1) atomicOr(&sbits[r1], m1);
    __syncthreads();

    if (tid < 64)
        g_bits[((size_t)(b * N + ti * 64 + tid)) * NW + tj] = sbits[tid];
}

// ---------------- 4. sequential greedy scan over the bit matrix -------------
__global__ void scan_kernel() {
    const int b    = blockIdx.x;
    const int lane = threadIdx.x;
    const unsigned long long* rows = g_bits + (size_t)b * N * NW;
    const int*   order = g_order + b * N;
    float*       keepf = g_keep  + b * N;

    unsigned long long sup0 = 0ull, sup1 = 0ull;
    unsigned long long r0 = rows[lane], r1 = rows[lane + 32];
    int ord = order[0];

    for (int i = 0; i < N; i++) {
        unsigned long long n0 = 0ull, n1 = 0ull;
        int nord = 0;
        if (i + 1 < N) {
            n0 = rows[(size_t)(i + 1) * NW + lane];
            n1 = rows[(size_t)(i + 1) * NW + lane + 32];
            nord = order[i + 1];
        }
        const int wsel = i >> 6;
        const unsigned long long sel = (wsel >= 32) ? sup1 : sup0;
        const unsigned long long sw  = __shfl_sync(0xffffffffu, sel, wsel & 31);
        const bool keep = ((sw >> (i & 63)) & 1ull) == 0ull;
        if (lane == 0) keepf[ord] = keep ? 1.0f : 0.0f;
        const unsigned long long m = keep ? ~0ull : 0ull;
        sup0 |= r0 & m;
        sup1 |= r1 & m;
        r0 = n0; r1 = n1; ord = nord;
    }
}

// ---------------- 5. outputs -------------------------------------------------
__global__ void mask_kernel(const float4* __restrict__ tok, float4* __restrict__ out) {
    const int idx = blockIdx.x * blockDim.x + threadIdx.x;
    if (idx >= B * N * (D / 4)) return;
    const float k = g_keep[idx >> 6];
    float4 v = tok[idx];
    v.x *= k; v.y *= k; v.z *= k; v.w *= k;
    out[idx] = v;
}

__global__ void keep_out_kernel(float* __restrict__ out, int count) {
    const int t = blockIdx.x * blockDim.x + threadIdx.x;
    if (t < count) out[t] = g_keep[t];
}

// ---------------- launch -----------------------------------------------------
extern "C" void kernel_launch(void* const* d_in, const int* in_sizes, int n_in,
                              void* d_out, int out_size) {
    const float* tokens = (const float*)d_in[0];
    const float* scores = (const float*)d_in[1];
    float* out = (float*)d_out;

    {
        dim3 grid(B, 4);
        rank_kernel<<<grid, 1024>>>(scores);
    }

    {
        const int warps  = B * N;
        const int thr    = 256;
        const int blocks = (warps * 32 + thr - 1) / thr;
        norm_gather_kernel<<<blocks, thr>>>(tokens);
    }

    {
        dim3 grid(NW, NW, B);
        sim_bits_kernel<<<grid, 256>>>();
    }

    scan_kernel<<<B, 32>>>();

    {
        const int total4 = B * N * (D / 4);
        mask_kernel<<<(total4 + 255) / 256, 256>>>((const float4*)tokens, (float4*)out);
    }

    const long long bnd = (long long)B * N * D;
    if ((long long)out_size > bnd) {
        int extra = (int)((long long)out_size - bnd);
        if (extra > B * N) extra = B * N;
        keep_out_kernel<<<(extra + 255) / 256, 256>>>(out + bnd, extra);
    }
}

// round 4
// speedup vs baseline: 3.8485x; 1.5010x over previous
#include <cuda_runtime.h>
#include <cuda_bf16.h>
#include <cstdint>

#define B 4
#define N 4096
#define D 256
#define NW 64               // 64-bit words per bit-row
#define NT 32               // 128-token tiles per batch
#define NPAIR 528           // NT*(NT+1)/2 upper-tri tile pairs
#define SIM_THR 0.7f
#define LDK 136             // smem row stride in bf16 for a 128-col chunk (272B)

// smem layout (bytes)
#define ABUF (128 * LDK * 2)            // 34816
#define SM_A0 0
#define SM_B0 (ABUF)
#define SM_A1 (2 * ABUF)
#define SM_B1 (3 * ABUF)
#define SM_BITS (4 * ABUF)              // 139264
#define SIM_SMEM (SM_BITS + 256 * 8)    // 141312

// ---------------- device scratch (zero-initialized at module load) ----------
__device__ __nv_bfloat16      g_sorted[(size_t)B * N * D];
__device__ int                g_order[B * N];
__device__ unsigned long long g_bits[(size_t)B * N * NW];
__device__ float              g_keep[B * N];

// ---------------- 1. rank by counting (stable argsort of -scores) ----------
__global__ void rank_kernel(const float* __restrict__ scores) {
    __shared__ float s[N];
    const int b = blockIdx.x, chunk = blockIdx.y, tid = threadIdx.x;  // 128 thr
    const float* sc = scores + b * N;
    for (int t = tid; t < N; t += 128) s[t] = sc[t];
    __syncthreads();
    const int   idx = chunk * 128 + tid;
    const float si  = s[idx];
    int rank = 0;
    #pragma unroll 8
    for (int j = 0; j < N; j++) {
        const float sj = s[j];
        rank += (sj > si) || (sj == si && j < idx);
    }
    g_order[b * N + rank] = idx;
}

// ---------------- 2. normalize + gather into sorted order (fp32 -> bf16) ----
__device__ inline unsigned pack_bf2(float a, float b) {
    __nv_bfloat162 h = __floats2bfloat162_rn(a, b);
    return *reinterpret_cast<unsigned*>(&h);
}
__global__ void norm_gather_kernel(const float* __restrict__ tokens) {
    const int gw   = (blockIdx.x * blockDim.x + threadIdx.x) >> 5;
    const int lane = threadIdx.x & 31;
    if (gw >= B * N) return;
    const int src_i = g_order[gw];
    const int b     = gw / N;
    const float* src = tokens + ((size_t)b * N + src_i) * D;
    float4 v0 = *(const float4*)(src + lane * 8);
    float4 v1 = *(const float4*)(src + lane * 8 + 4);
    float ss = v0.x*v0.x + v0.y*v0.y + v0.z*v0.z + v0.w*v0.w
             + v1.x*v1.x + v1.y*v1.y + v1.z*v1.z + v1.w*v1.w;
    #pragma unroll
    for (int o = 16; o > 0; o >>= 1) ss += __shfl_xor_sync(0xffffffffu, ss, o);
    const float inv = 1.0f / (sqrtf(ss) + 1e-6f);
    uint4 u;
    u.x = pack_bf2(v0.x * inv, v0.y * inv);
    u.y = pack_bf2(v0.z * inv, v0.w * inv);
    u.z = pack_bf2(v1.x * inv, v1.y * inv);
    u.w = pack_bf2(v1.z * inv, v1.w * inv);
    *(uint4*)(g_sorted + (size_t)gw * D + lane * 8) = u;
}

// ---------------- 3. HMMA similarity: 128x128 tiles -> suppression bits -----
__device__ __forceinline__ void cp_async16(uint32_t saddr, const void* gaddr) {
    asm volatile("cp.async.cg.shared.global [%0], [%1], 16;"
                 :: "r"(saddr), "l"(gaddr));
}
__device__ __forceinline__ void ldm_x4(uint32_t& r0, uint32_t& r1,
                                       uint32_t& r2, uint32_t& r3, uint32_t addr) {
    asm volatile("ldmatrix.sync.aligned.m8n8.x4.shared.b16 {%0,%1,%2,%3}, [%4];"
                 : "=r"(r0), "=r"(r1), "=r"(r2), "=r"(r3) : "r"(addr));
}
__device__ __forceinline__ void mma16816(float c[4], uint32_t a0, uint32_t a1,
                                         uint32_t a2, uint32_t a3,
                                         uint32_t b0, uint32_t b1) {
    asm volatile("mma.sync.aligned.m16n8k16.row.col.f32.bf16.bf16.f32 "
                 "{%0,%1,%2,%3}, {%4,%5,%6,%7}, {%8,%9}, {%0,%1,%2,%3};"
                 : "+f"(c[0]), "+f"(c[1]), "+f"(c[2]), "+f"(c[3])
                 : "r"(a0), "r"(a1), "r"(a2), "r"(a3), "r"(b0), "r"(b1));
}

__device__ __forceinline__ void compute_chunk(
    uint32_t baseA, uint32_t baseB, int wm, int wn, int lane, float acc[4][4][4]) {
    #pragma unroll
    for (int ks = 0; ks < 8; ks++) {
        uint32_t a[4][4];
        #pragma unroll
        for (int tm = 0; tm < 4; tm++) {
            const int row  = wm * 64 + tm * 16 + (lane & 15);
            const int col  = ks * 16 + ((lane >> 4) << 3);
            ldm_x4(a[tm][0], a[tm][1], a[tm][2], a[tm][3],
                   baseA + (uint32_t)(row * LDK + col) * 2);
        }
        #pragma unroll
        for (int p = 0; p < 2; p++) {
            const int row = wn * 32 + p * 16 + (lane & 7) + ((lane >> 4) << 3);
            const int col = ks * 16 + (((lane >> 3) & 1) << 3);
            uint32_t b0, b1, b2, b3;
            ldm_x4(b0, b1, b2, b3, baseB + (uint32_t)(row * LDK + col) * 2);
            #pragma unroll
            for (int tm = 0; tm < 4; tm++) {
                mma16816(acc[tm][p*2],   a[tm][0], a[tm][1], a[tm][2], a[tm][3], b0, b1);
                mma16816(acc[tm][p*2+1], a[tm][0], a[tm][1], a[tm][2], a[tm][3], b2, b3);
            }
        }
    }
}

__global__ void __launch_bounds__(256, 1) sim_bits_kernel() {
    // decode upper-tri pair (ti <= tj)
    int rem = blockIdx.x, ti = 0;
    while (rem >= NT - ti) { rem -= NT - ti; ti++; }
    const int tj = ti + rem;
    const int b  = blockIdx.y;

    extern __shared__ __align__(128) char sm[];
    const uint32_t smb = (uint32_t)__cvta_generic_to_shared(sm);
    unsigned long long* sbits = (unsigned long long*)(sm + SM_BITS);

    const int tid = threadIdx.x, lane = tid & 31, wid = tid >> 5;
    const int wm = wid & 1, wn = wid >> 1;

    const __nv_bfloat16* Ab = g_sorted + ((size_t)b * N + ti * 128) * D;
    const __nv_bfloat16* Bb = g_sorted + ((size_t)b * N + tj * 128) * D;

    // stage both K-chunks with cp.async (two commit groups)
    #pragma unroll
    for (int c = 0; c < 2; c++) {
        const int kc   = c * 128;
        const uint32_t sa = smb + (c ? SM_A1 : SM_A0);
        const uint32_t sb = smb + (c ? SM_B1 : SM_B0);
        #pragma unroll
        for (int l = 0; l < 8; l++) {
            const int e   = tid + l * 256;      // 2048 16B-chunks per tile
            const int row = e >> 4;
            const int c8  = (e & 15) * 8;       // bf16 col within chunk
            const uint32_t so = (uint32_t)(row * LDK + c8) * 2;
            cp_async16(sa + so, Ab + row * D + kc + c8);
            cp_async16(sb + so, Bb + row * D + kc + c8);
        }
        asm volatile("cp.async.commit_group;");
    }

    sbits[tid] = 0ull;

    float acc[4][4][4] = {};

    asm volatile("cp.async.wait_group 1;");
    __syncthreads();
    compute_chunk(smb + SM_A0, smb + SM_B0, wm, wn, lane, acc);

    asm volatile("cp.async.wait_group 0;");
    __syncthreads();
    compute_chunk(smb + SM_A1, smb + SM_B1, wm, wn, lane, acc);

    // epilogue: threshold -> bits
    const int word = wn >> 1;                    // which 64-col word of the tile
    #pragma unroll
    for (int tm = 0; tm < 4; tm++) {
        const int r0  = wm * 64 + tm * 16 + (lane >> 2);
        const int r1  = r0 + 8;
        const int gi0 = ti * 128 + r0;
        const int gi1 = ti * 128 + r1;
        unsigned long long m0 = 0ull, m1 = 0ull;
        #pragma unroll
        for (int nt = 0; nt < 4; nt++) {
            const int lc = wn * 32 + nt * 8 + ((lane & 3) << 1);  // 0..127
            const int gj = tj * 128 + lc;
            const int bp = lc & 63;
            if (acc[tm][nt][0] > SIM_THR && gj     > gi0) m0 |= 1ull << bp;
            if (acc[tm][nt][1] > SIM_THR && gj + 1 > gi0) m0 |= 1ull << (bp + 1);
            if (acc[tm][nt][2] > SIM_THR && gj     > gi1) m1 |= 1ull << bp;
            if (acc[tm][nt][3] > SIM_THR && gj + 1 > gi1) m1 |= 1ull << (bp + 1);
        }
        if (m0) atomicOr(&sbits[r0 * 2 + word], m0);
        if (m1) atomicOr(&sbits[r1 * 2 + word], m1);
    }
    __syncthreads();

    const int row = tid >> 1, w = tid & 1;
    g_bits[((size_t)(b * N + ti * 128 + row)) * NW + tj * 2 + w] = sbits[tid];
}

// ---------------- 4. greedy scan: smem diag blocks, register chain ----------
__global__ void scan_kernel() {
    __shared__ unsigned long long diag[64 * 64];
    __shared__ unsigned long long blk_or[64];
    const int b    = blockIdx.x;
    const int lane = threadIdx.x;                  // 32 threads
    const unsigned long long* rows = g_bits + (size_t)b * N * NW;
    const int*   order = g_order + b * N;
    float*       keepf = g_keep  + b * N;

    for (int e = lane; e < 64 * 64; e += 32) {
        const int wb = e >> 6, i = e & 63;
        diag[e] = rows[(size_t)(wb * 64 + i) * NW + wb];
    }
    __syncwarp();
    for (int wb = 0; wb < 64; wb++) {
        unsigned long long v = diag[wb * 64 + lane] | diag[wb * 64 + 32 + lane];
        #pragma unroll
        for (int o = 16; o > 0; o >>= 1) v |= __shfl_xor_sync(0xffffffffu, v, o);
        if (lane == 0) blk_or[wb] = v;
    }
    __syncwarp();

    unsigned long long sup0 = 0ull, sup1 = 0ull;   // lane owns words lane, lane+32
    for (int wb = 0; wb < 64; wb++) {
        unsigned long long supw =
            __shfl_sync(0xffffffffu, (wb < 32) ? sup0 : sup1, wb & 31);
        unsigned long long keepm;
        if (blk_or[wb] == 0ull) {
            keepm = ~supw;
        } else {
            keepm = 0ull;                           // redundant on all lanes
            #pragma unroll 8
            for (int i = 0; i < 64; i++) {
                const unsigned long long d = diag[wb * 64 + i];
                const bool k = ((supw >> i) & 1ull) == 0ull;
                if (k) { supw |= d; keepm |= 1ull << i; }
            }
        }
        const int t0 = wb * 64 + lane;
        keepf[order[t0]]      = ((keepm >> lane)        & 1ull) ? 1.0f : 0.0f;
        keepf[order[t0 + 32]] = ((keepm >> (lane + 32)) & 1ull) ? 1.0f : 0.0f;

        for (int i = 0; i < 64; i++) {
            if ((keepm >> i) & 1ull) {
                const size_t ro = (size_t)(wb * 64 + i) * NW;
                sup0 |= rows[ro + lane];
                sup1 |= rows[ro + lane + 32];
            }
        }
    }
}

// ---------------- 5. outputs -------------------------------------------------
__global__ void mask_kernel(const float4* __restrict__ tok, float4* __restrict__ out) {
    const int idx = blockIdx.x * blockDim.x + threadIdx.x;
    if (idx >= B * N * (D / 4)) return;
    const float k = g_keep[idx >> 6];
    float4 v = tok[idx];
    v.x *= k; v.y *= k; v.z *= k; v.w *= k;
    out[idx] = v;
}
__global__ void keep_out_kernel(float* __restrict__ out, int count) {
    const int t = blockIdx.x * blockDim.x + threadIdx.x;
    if (t < count) out[t] = g_keep[t];
}

// ---------------- launch -----------------------------------------------------
extern "C" void kernel_launch(void* const* d_in, const int* in_sizes, int n_in,
                              void* d_out, int out_size) {
    const float* tokens = (const float*)d_in[0];
    const float* scores = (const float*)d_in[1];
    float* out = (float*)d_out;

    cudaFuncSetAttribute(sim_bits_kernel,
                         cudaFuncAttributeMaxDynamicSharedMemorySize, SIM_SMEM);

    { dim3 grid(B, 32); rank_kernel<<<grid, 128>>>(scores); }

    {
        const int warps  = B * N;
        const int blocks = (warps * 32 + 255) / 256;
        norm_gather_kernel<<<blocks, 256>>>(tokens);
    }

    { dim3 grid(NPAIR, B); sim_bits_kernel<<<grid, 256, SIM_SMEM>>>(); }

    scan_kernel<<<B, 32>>>();

    {
        const int total4 = B * N * (D / 4);
        mask_kernel<<<(total4 + 255) / 256, 256>>>((const float4*)tokens, (float4*)out);
    }

    const long long bnd = (long long)B * N * D;
    if ((long long)out_size > bnd) {
        int extra = (int)((long long)out_size - bnd);
        if (extra > B * N) extra = B * N;
        keep_out_kernel<<<(extra + 255) / 256, 256>>>(out + bnd, extra);
    }
}

// round 5
// speedup vs baseline: 13.1777x; 3.4241x over previous
#include <cuda_runtime.h>
#include <cuda_bf16.h>
#include <cstdint>

#define B 4
#define N 4096
#define D 256
#define NW 64               // 64-bit words per bit-row
#define NT 32               // 128-token tiles per batch
#define NPAIR 528           // NT*(NT+1)/2 upper-tri tile pairs
#define SIM_THR 0.7f
#define LDK 136             // smem row stride in bf16 for a 128-col chunk (272B)

typedef unsigned long long ull;

// ---------------- smem layout for sim kernel (bytes) ------------------------
#define ABUF (128 * LDK * 2)            // 34816
#define SM_A0 0
#define SM_B0 (ABUF)
#define SM_A1 (2 * ABUF)
#define SM_B1 (3 * ABUF)
#define SM_BITS (4 * ABUF)              // 139264
#define SIM_SMEM (SM_BITS + 256 * 8)    // 141312

// ---------------- smem layout for scan kernel (ull units) -------------------
// buf0[4096] buf1[4096] sup[64] keepm[1] order[2048 ull = 4096 int]
#define SC_BUF0 0
#define SC_BUF1 4096
#define SC_SUP  8192
#define SC_KM   (SC_SUP + 64)
#define SC_ORD  (SC_KM + 1)
#define SCAN_SMEM ((SC_ORD + 2048) * 8)   // ~82.5 KB

// ---------------- device scratch (zero-initialized at module load) ----------
__device__ __nv_bfloat16 g_sorted[(size_t)B * N * D];
__device__ int           g_order[B * N];
__device__ ull           g_bits[(size_t)B * N * NW];
__device__ float         g_keep[B * N];

// ---------------- 1. rank by counting (stable argsort of -scores) ----------
__global__ void rank_kernel(const float* __restrict__ scores) {
    __shared__ float s[N];
    const int b = blockIdx.x, chunk = blockIdx.y, tid = threadIdx.x;  // 128 thr
    const float* sc = scores + b * N;
    for (int t = tid; t < N; t += 128) s[t] = sc[t];
    __syncthreads();
    const int   idx = chunk * 128 + tid;
    const float si  = s[idx];
    int rank = 0;
    #pragma unroll 8
    for (int j = 0; j < N; j++) {
        const float sj = s[j];
        rank += (sj > si) || (sj == si && j < idx);
    }
    g_order[b * N + rank] = idx;
}

// ---------------- 2. normalize + gather into sorted order (fp32 -> bf16) ----
__device__ inline unsigned pack_bf2(float a, float b) {
    __nv_bfloat162 h = __floats2bfloat162_rn(a, b);
    return *reinterpret_cast<unsigned*>(&h);
}
__global__ void norm_gather_kernel(const float* __restrict__ tokens) {
    const int gw   = (blockIdx.x * blockDim.x + threadIdx.x) >> 5;
    const int lane = threadIdx.x & 31;
    if (gw >= B * N) return;
    const int src_i = g_order[gw];
    const int b     = gw / N;
    const float* src = tokens + ((size_t)b * N + src_i) * D;
    float4 v0 = *(const float4*)(src + lane * 8);
    float4 v1 = *(const float4*)(src + lane * 8 + 4);
    float ss = v0.x*v0.x + v0.y*v0.y + v0.z*v0.z + v0.w*v0.w
             + v1.x*v1.x + v1.y*v1.y + v1.z*v1.z + v1.w*v1.w;
    #pragma unroll
    for (int o = 16; o > 0; o >>= 1) ss += __shfl_xor_sync(0xffffffffu, ss, o);
    const float inv = 1.0f / (sqrtf(ss) + 1e-6f);
    uint4 u;
    u.x = pack_bf2(v0.x * inv, v0.y * inv);
    u.y = pack_bf2(v0.z * inv, v0.w * inv);
    u.z = pack_bf2(v1.x * inv, v1.y * inv);
    u.w = pack_bf2(v1.z * inv, v1.w * inv);
    *(uint4*)(g_sorted + (size_t)gw * D + lane * 8) = u;
}

// ---------------- 3. HMMA similarity: 128x128 tiles -> suppression bits -----
__device__ __forceinline__ void cp_async16(uint32_t saddr, const void* gaddr) {
    asm volatile("cp.async.cg.shared.global [%0], [%1], 16;"
                 :: "r"(saddr), "l"(gaddr));
}
__device__ __forceinline__ void ldm_x4(uint32_t& r0, uint32_t& r1,
                                       uint32_t& r2, uint32_t& r3, uint32_t addr) {
    asm volatile("ldmatrix.sync.aligned.m8n8.x4.shared.b16 {%0,%1,%2,%3}, [%4];"
                 : "=r"(r0), "=r"(r1), "=r"(r2), "=r"(r3) : "r"(addr));
}
__device__ __forceinline__ void mma16816(float c[4], uint32_t a0, uint32_t a1,
                                         uint32_t a2, uint32_t a3,
                                         uint32_t b0, uint32_t b1) {
    asm volatile("mma.sync.aligned.m16n8k16.row.col.f32.bf16.bf16.f32 "
                 "{%0,%1,%2,%3}, {%4,%5,%6,%7}, {%8,%9}, {%0,%1,%2,%3};"
                 : "+f"(c[0]), "+f"(c[1]), "+f"(c[2]), "+f"(c[3])
                 : "r"(a0), "r"(a1), "r"(a2), "r"(a3), "r"(b0), "r"(b1));
}

__device__ __forceinline__ void compute_chunk(
    uint32_t baseA, uint32_t baseB, int wm, int wn, int lane, float acc[4][4][4]) {
    #pragma unroll
    for (int ks = 0; ks < 8; ks++) {
        uint32_t a[4][4];
        #pragma unroll
        for (int tm = 0; tm < 4; tm++) {
            const int row  = wm * 64 + tm * 16 + (lane & 15);
            const int col  = ks * 16 + ((lane >> 4) << 3);
            ldm_x4(a[tm][0], a[tm][1], a[tm][2], a[tm][3],
                   baseA + (uint32_t)(row * LDK + col) * 2);
        }
        #pragma unroll
        for (int p = 0; p < 2; p++) {
            const int row = wn * 32 + p * 16 + (lane & 7) + ((lane >> 4) << 3);
            const int col = ks * 16 + (((lane >> 3) & 1) << 3);
            uint32_t b0, b1, b2, b3;
            ldm_x4(b0, b1, b2, b3, baseB + (uint32_t)(row * LDK + col) * 2);
            #pragma unroll
            for (int tm = 0; tm < 4; tm++) {
                mma16816(acc[tm][p*2],   a[tm][0], a[tm][1], a[tm][2], a[tm][3], b0, b1);
                mma16816(acc[tm][p*2+1], a[tm][0], a[tm][1], a[tm][2], a[tm][3], b2, b3);
            }
        }
    }
}

__global__ void __launch_bounds__(256, 1) sim_bits_kernel() {
    int rem = blockIdx.x, ti = 0;
    while (rem >= NT - ti) { rem -= NT - ti; ti++; }
    const int tj = ti + rem;
    const int b  = blockIdx.y;

    extern __shared__ __align__(128) char sm[];
    const uint32_t smb = (uint32_t)__cvta_generic_to_shared(sm);
    ull* sbits = (ull*)(sm + SM_BITS);

    const int tid = threadIdx.x, lane = tid & 31, wid = tid >> 5;
    const int wm = wid & 1, wn = wid >> 1;

    const __nv_bfloat16* Ab = g_sorted + ((size_t)b * N + ti * 128) * D;
    const __nv_bfloat16* Bb = g_sorted + ((size_t)b * N + tj * 128) * D;

    #pragma unroll
    for (int c = 0; c < 2; c++) {
        const int kc   = c * 128;
        const uint32_t sa = smb + (c ? SM_A1 : SM_A0);
        const uint32_t sb = smb + (c ? SM_B1 : SM_B0);
        #pragma unroll
        for (int l = 0; l < 8; l++) {
            const int e   = tid + l * 256;
            const int row = e >> 4;
            const int c8  = (e & 15) * 8;
            const uint32_t so = (uint32_t)(row * LDK + c8) * 2;
            cp_async16(sa + so, Ab + row * D + kc + c8);
            cp_async16(sb + so, Bb + row * D + kc + c8);
        }
        asm volatile("cp.async.commit_group;");
    }

    sbits[tid] = 0ull;

    float acc[4][4][4] = {};

    asm volatile("cp.async.wait_group 1;");
    __syncthreads();
    compute_chunk(smb + SM_A0, smb + SM_B0, wm, wn, lane, acc);

    asm volatile("cp.async.wait_group 0;");
    __syncthreads();
    compute_chunk(smb + SM_A1, smb + SM_B1, wm, wn, lane, acc);

    const int word = wn >> 1;
    #pragma unroll
    for (int tm = 0; tm < 4; tm++) {
        const int r0  = wm * 64 + tm * 16 + (lane >> 2);
        const int r1  = r0 + 8;
        const int gi0 = ti * 128 + r0;
        const int gi1 = ti * 128 + r1;
        ull m0 = 0ull, m1 = 0ull;
        #pragma unroll
        for (int nt = 0; nt < 4; nt++) {
            const int lc = wn * 32 + nt * 8 + ((lane & 3) << 1);
            const int gj = tj * 128 + lc;
            const int bp = lc & 63;
            if (acc[tm][nt][0] > SIM_THR && gj     > gi0) m0 |= 1ull << bp;
            if (acc[tm][nt][1] > SIM_THR && gj + 1 > gi0) m0 |= 1ull << (bp + 1);
            if (acc[tm][nt][2] > SIM_THR && gj     > gi1) m1 |= 1ull << bp;
            if (acc[tm][nt][3] > SIM_THR && gj + 1 > gi1) m1 |= 1ull << (bp + 1);
        }
        if (m0) atomicOr(&sbits[r0 * 2 + word], m0);
        if (m1) atomicOr(&sbits[r1 * 2 + word], m1);
    }
    __syncthreads();

    const int row = tid >> 1, w = tid & 1;
    g_bits[((size_t)(b * N + ti * 128 + row)) * NW + tj * 2 + w] = sbits[tid];
}

// ---------------- 4. greedy scan: 1024 threads, cp.async double buffer ------
__global__ void __launch_bounds__(1024, 1) scan_kernel() {
    extern __shared__ __align__(16) ull ssm[];
    ull*  sup      = ssm + SC_SUP;
    ull*  sh_keepm = ssm + SC_KM;
    int*  sord     = (int*)(ssm + SC_ORD);

    const int b   = blockIdx.x;
    const int tid = threadIdx.x;
    const ull* rows = g_bits + (size_t)b * N * NW;
    const int* order = g_order + b * N;
    float*     keepf = g_keep  + b * N;

    if (tid < 64) sup[tid] = 0ull;
    #pragma unroll
    for (int l = 0; l < 4; l++) sord[tid + l * 1024] = order[tid + l * 1024];

    const uint32_t smb = (uint32_t)__cvta_generic_to_shared(ssm);
    // prefetch block 0 (32 KB = 2048 x 16B)
    {
        const char* src = (const char*)rows;
        cp_async16(smb + (uint32_t)tid * 16,          src + tid * 16);
        cp_async16(smb + (uint32_t)(tid + 1024) * 16, src + (tid + 1024) * 16);
        asm volatile("cp.async.commit_group;");
    }

    for (int wb = 0; wb < 64; wb++) {
        asm volatile("cp.async.wait_group 0;");
        __syncthreads();
        ull* cur = ssm + ((wb & 1) ? SC_BUF1 : SC_BUF0);

        if (wb + 1 < 64) {
            const uint32_t dst = smb + (uint32_t)(((wb + 1) & 1) ? SC_BUF1 : SC_BUF0) * 8;
            const char* src = (const char*)(rows + (size_t)(wb + 1) * 64 * NW);
            cp_async16(dst + (uint32_t)tid * 16,          src + tid * 16);
            cp_async16(dst + (uint32_t)(tid + 1024) * 16, src + (tid + 1024) * 16);
            asm volatile("cp.async.commit_group;");
        }

        // phase A (warp 0): intra-block keep chain
        if (tid < 32) {
            const int lane = tid;
            const ull d0 = cur[lane * 64 + wb];
            const ull d1 = cur[(lane + 32) * 64 + wb];
            ull v = d0 | d1;
            #pragma unroll
            for (int o = 16; o > 0; o >>= 1) v |= __shfl_xor_sync(0xffffffffu, v, o);
            ull supw = sup[wb];
            ull keepm;
            if (v == 0ull) {
                keepm = ~supw;
            } else {
                keepm = 0ull;                       // redundant per-lane, no shfl in chain
                #pragma unroll 8
                for (int i = 0; i < 64; i++) {
                    const ull d = cur[i * 64 + wb];
                    const bool k = ((supw >> i) & 1ull) == 0ull;
                    if (k) { supw |= d; keepm |= 1ull << i; }
                }
            }
            const int t0 = wb * 64 + lane;
            keepf[sord[t0]]      = ((keepm >> lane)        & 1ull) ? 1.0f : 0.0f;
            keepf[sord[t0 + 32]] = ((keepm >> (lane + 32)) & 1ull) ? 1.0f : 0.0f;
            if (lane == 0) sh_keepm[0] = keepm;
        }
        __syncthreads();

        // phase B (all 1024): sup[w] |= OR of kept rows, words w > wb only
        const ull keepm = sh_keepm[0];
        const int w   = tid & 63;
        const int sub = tid >> 6;                   // 16 groups x 4 rows
        if (w > wb) {
            ull p = 0ull;
            #pragma unroll
            for (int r = 0; r < 4; r++) {
                const int i = sub * 4 + r;
                if ((keepm >> i) & 1ull) p |= cur[i * 64 + w];
            }
            if (p) atomicOr(&sup[w], p);
        }
        __syncthreads();
    }
}

// ---------------- 5. outputs -------------------------------------------------
__global__ void mask_kernel(const float4* __restrict__ tok, float4* __restrict__ out) {
    const int idx = blockIdx.x * blockDim.x + threadIdx.x;
    if (idx >= B * N * (D / 4)) return;
    const float k = g_keep[idx >> 6];
    float4 v = tok[idx];
    v.x *= k; v.y *= k; v.z *= k; v.w *= k;
    out[idx] = v;
}
__global__ void keep_out_kernel(float* __restrict__ out, int count) {
    const int t = blockIdx.x * blockDim.x + threadIdx.x;
    if (t < count) out[t] = g_keep[t];
}

// ---------------- launch -----------------------------------------------------
extern "C" void kernel_launch(void* const* d_in, const int* in_sizes, int n_in,
                              void* d_out, int out_size) {
    const float* tokens = (const float*)d_in[0];
    const float* scores = (const float*)d_in[1];
    float* out = (float*)d_out;

    cudaFuncSetAttribute(sim_bits_kernel,
                         cudaFuncAttributeMaxDynamicSharedMemorySize, SIM_SMEM);
    cudaFuncSetAttribute(scan_kernel,
                         cudaFuncAttributeMaxDynamicSharedMemorySize, SCAN_SMEM);

    { dim3 grid(B, 32); rank_kernel<<<grid, 128>>>(scores); }

    {
        const int warps  = B * N;
        const int blocks = (warps * 32 + 255) / 256;
        norm_gather_kernel<<<blocks, 256>>>(tokens);
    }

    { dim3 grid(NPAIR, B); sim_bits_kernel<<<grid, 256, SIM_SMEM>>>(); }

    scan_kernel<<<B, 1024, SCAN_SMEM>>>();

    {
        const int total4 = B * N * (D / 4);
        mask_kernel<<<(total4 + 255) / 256, 256>>>((const float4*)tokens, (float4*)out);
    }

    const long long bnd = (long long)B * N * D;
    if ((long long)out_size > bnd) {
        int extra = (int)((long long)out_size - bnd);
        if (extra > B * N) extra = B * N;
        keep_out_kernel<<<(extra + 255) / 256, 256>>>(out + bnd, extra);
    }
}

// round 6
// speedup vs baseline: 17.1744x; 1.3033x over previous
#include <cuda_runtime.h>
#include <cuda_bf16.h>
#include <cstdint>

#define B 4
#define N 4096
#define D 256
#define NW 64               // 64-bit words per bit-row
#define NT 32               // 128-token tiles per batch
#define NPAIR 528           // NT*(NT+1)/2 upper-tri tile pairs
#define SIM_THR 0.7f
#define LDK 136             // smem row stride in bf16 for a 128-col chunk (272B)

typedef unsigned long long ull;

// ---------------- smem layout for sim kernel (bytes) ------------------------
#define ABUF (128 * LDK * 2)            // 34816
#define SM_A0 0
#define SM_B0 (ABUF)
#define SM_A1 (2 * ABUF)
#define SM_B1 (3 * ABUF)
#define SM_BITS (4 * ABUF)              // 139264
#define SM_FLAG (SM_BITS + 256 * 8)     // 4 uint flags
#define SIM_SMEM (SM_FLAG + 16)

// ---------------- smem layout for scan kernel (ull units) -------------------
// buf[4096] sup[64] flags[64] keepm[1] order[2048 ull = 4096 int]
#define SC_BUF  0
#define SC_SUP  4096
#define SC_FLG  (SC_SUP + 64)
#define SC_KM   (SC_FLG + 64)
#define SC_ORD  (SC_KM + 1)
#define SCAN_SMEM ((SC_ORD + 2048) * 8)   // ~50.2 KB

// ---------------- device scratch (zero-initialized at module load) ----------
__device__ __nv_bfloat16 g_sorted[(size_t)B * N * D];
__device__ int           g_order[B * N];
__device__ ull           g_bits[(size_t)B * N * NW];
__device__ ull           g_blkflag[B][64];    // bit w of [b][rb]: block (rb,w) nonzero
__device__ float         g_keep[B * N];

// ---------------- 1. rank by counting + flag reset ---------------------------
__global__ void rank_kernel(const float* __restrict__ scores) {
    __shared__ float s[N];
    const int b = blockIdx.x, chunk = blockIdx.y, tid = threadIdx.x;  // 128 thr
    if (chunk == 0 && tid < 64) g_blkflag[b][tid] = 0ull;
    const float* sc = scores + b * N;
    for (int t = tid; t < N; t += 128) s[t] = sc[t];
    __syncthreads();
    const int   idx = chunk * 128 + tid;
    const float si  = s[idx];
    int rank = 0;
    #pragma unroll 8
    for (int j = 0; j < N; j++) {
        const float sj = s[j];
        rank += (sj > si) || (sj == si && j < idx);
    }
    g_order[b * N + rank] = idx;
}

// ---------------- 2. normalize + gather into sorted order (fp32 -> bf16) ----
__device__ inline unsigned pack_bf2(float a, float b) {
    __nv_bfloat162 h = __floats2bfloat162_rn(a, b);
    return *reinterpret_cast<unsigned*>(&h);
}
__global__ void norm_gather_kernel(const float* __restrict__ tokens) {
    const int gw   = (blockIdx.x * blockDim.x + threadIdx.x) >> 5;
    const int lane = threadIdx.x & 31;
    if (gw >= B * N) return;
    const int src_i = g_order[gw];
    const int b     = gw / N;
    const float* src = tokens + ((size_t)b * N + src_i) * D;
    float4 v0 = *(const float4*)(src + lane * 8);
    float4 v1 = *(const float4*)(src + lane * 8 + 4);
    float ss = v0.x*v0.x + v0.y*v0.y + v0.z*v0.z + v0.w*v0.w
             + v1.x*v1.x + v1.y*v1.y + v1.z*v1.z + v1.w*v1.w;
    #pragma unroll
    for (int o = 16; o > 0; o >>= 1) ss += __shfl_xor_sync(0xffffffffu, ss, o);
    const float inv = 1.0f / (sqrtf(ss) + 1e-6f);
    uint4 u;
    u.x = pack_bf2(v0.x * inv, v0.y * inv);
    u.y = pack_bf2(v0.z * inv, v0.w * inv);
    u.z = pack_bf2(v1.x * inv, v1.y * inv);
    u.w = pack_bf2(v1.z * inv, v1.w * inv);
    *(uint4*)(g_sorted + (size_t)gw * D + lane * 8) = u;
}

// ---------------- 3. HMMA similarity: 128x128 tiles -> bits + flags ---------
__device__ __forceinline__ void cp_async16(uint32_t saddr, const void* gaddr) {
    asm volatile("cp.async.cg.shared.global [%0], [%1], 16;"
                 :: "r"(saddr), "l"(gaddr));
}
__device__ __forceinline__ void ldm_x4(uint32_t& r0, uint32_t& r1,
                                       uint32_t& r2, uint32_t& r3, uint32_t addr) {
    asm volatile("ldmatrix.sync.aligned.m8n8.x4.shared.b16 {%0,%1,%2,%3}, [%4];"
                 : "=r"(r0), "=r"(r1), "=r"(r2), "=r"(r3) : "r"(addr));
}
__device__ __forceinline__ void mma16816(float c[4], uint32_t a0, uint32_t a1,
                                         uint32_t a2, uint32_t a3,
                                         uint32_t b0, uint32_t b1) {
    asm volatile("mma.sync.aligned.m16n8k16.row.col.f32.bf16.bf16.f32 "
                 "{%0,%1,%2,%3}, {%4,%5,%6,%7}, {%8,%9}, {%0,%1,%2,%3};"
                 : "+f"(c[0]), "+f"(c[1]), "+f"(c[2]), "+f"(c[3])
                 : "r"(a0), "r"(a1), "r"(a2), "r"(a3), "r"(b0), "r"(b1));
}

__device__ __forceinline__ void compute_chunk(
    uint32_t baseA, uint32_t baseB, int wm, int wn, int lane, float acc[4][4][4]) {
    #pragma unroll
    for (int ks = 0; ks < 8; ks++) {
        uint32_t a[4][4];
        #pragma unroll
        for (int tm = 0; tm < 4; tm++) {
            const int row  = wm * 64 + tm * 16 + (lane & 15);
            const int col  = ks * 16 + ((lane >> 4) << 3);
            ldm_x4(a[tm][0], a[tm][1], a[tm][2], a[tm][3],
                   baseA + (uint32_t)(row * LDK + col) * 2);
        }
        #pragma unroll
        for (int p = 0; p < 2; p++) {
            const int row = wn * 32 + p * 16 + (lane & 7) + ((lane >> 4) << 3);
            const int col = ks * 16 + (((lane >> 3) & 1) << 3);
            uint32_t b0, b1, b2, b3;
            ldm_x4(b0, b1, b2, b3, baseB + (uint32_t)(row * LDK + col) * 2);
            #pragma unroll
            for (int tm = 0; tm < 4; tm++) {
                mma16816(acc[tm][p*2],   a[tm][0], a[tm][1], a[tm][2], a[tm][3], b0, b1);
                mma16816(acc[tm][p*2+1], a[tm][0], a[tm][1], a[tm][2], a[tm][3], b2, b3);
            }
        }
    }
}

__global__ void __launch_bounds__(256, 1) sim_bits_kernel() {
    int rem = blockIdx.x, ti = 0;
    while (rem >= NT - ti) { rem -= NT - ti; ti++; }
    const int tj = ti + rem;
    const int b  = blockIdx.y;

    extern __shared__ __align__(128) char sm[];
    const uint32_t smb = (uint32_t)__cvta_generic_to_shared(sm);
    ull*          sbits  = (ull*)(sm + SM_BITS);
    unsigned int* sflag  = (unsigned int*)(sm + SM_FLAG);

    const int tid = threadIdx.x, lane = tid & 31, wid = tid >> 5;
    const int wm = wid & 1, wn = wid >> 1;

    const __nv_bfloat16* Ab = g_sorted + ((size_t)b * N + ti * 128) * D;
    const __nv_bfloat16* Bb = g_sorted + ((size_t)b * N + tj * 128) * D;

    #pragma unroll
    for (int c = 0; c < 2; c++) {
        const int kc   = c * 128;
        const uint32_t sa = smb + (c ? SM_A1 : SM_A0);
        const uint32_t sb = smb + (c ? SM_B1 : SM_B0);
        #pragma unroll
        for (int l = 0; l < 8; l++) {
            const int e   = tid + l * 256;
            const int row = e >> 4;
            const int c8  = (e & 15) * 8;
            const uint32_t so = (uint32_t)(row * LDK + c8) * 2;
            cp_async16(sa + so, Ab + row * D + kc + c8);
            cp_async16(sb + so, Bb + row * D + kc + c8);
        }
        asm volatile("cp.async.commit_group;");
    }

    sbits[tid] = 0ull;
    if (tid < 4) sflag[tid] = 0u;

    float acc[4][4][4] = {};

    asm volatile("cp.async.wait_group 1;");
    __syncthreads();
    compute_chunk(smb + SM_A0, smb + SM_B0, wm, wn, lane, acc);

    asm volatile("cp.async.wait_group 0;");
    __syncthreads();
    compute_chunk(smb + SM_A1, smb + SM_B1, wm, wn, lane, acc);

    const int word = wn >> 1;
    #pragma unroll
    for (int tm = 0; tm < 4; tm++) {
        const int r0  = wm * 64 + tm * 16 + (lane >> 2);
        const int r1  = r0 + 8;
        const int gi0 = ti * 128 + r0;
        const int gi1 = ti * 128 + r1;
        ull m0 = 0ull, m1 = 0ull;
        #pragma unroll
        for (int nt = 0; nt < 4; nt++) {
            const int lc = wn * 32 + nt * 8 + ((lane & 3) << 1);
            const int gj = tj * 128 + lc;
            const int bp = lc & 63;
            if (acc[tm][nt][0] > SIM_THR && gj     > gi0) m0 |= 1ull << bp;
            if (acc[tm][nt][1] > SIM_THR && gj + 1 > gi0) m0 |= 1ull << (bp + 1);
            if (acc[tm][nt][2] > SIM_THR && gj     > gi1) m1 |= 1ull << bp;
            if (acc[tm][nt][3] > SIM_THR && gj + 1 > gi1) m1 |= 1ull << (bp + 1);
        }
        if (m0) atomicOr(&sbits[r0 * 2 + word], m0);
        if (m1) atomicOr(&sbits[r1 * 2 + word], m1);
    }
    __syncthreads();

    const int row = tid >> 1, w = tid & 1;
    const ull myword = sbits[tid];
    g_bits[((size_t)(b * N + ti * 128 + row)) * NW + tj * 2 + w] = myword;

    // hierarchical nonzero flags: group = (row-half, word)
    if (myword) atomicOr(&sflag[((row >> 6) << 1) | w], 1u);
    __syncthreads();
    if (tid < 4 && sflag[tid]) {
        const int rb = ti * 2 + (tid >> 1);
        const int wg = tj * 2 + (tid & 1);
        atomicOr(&g_blkflag[b][rb], 1ull << wg);
    }
}

// ---------------- 4. greedy scan with block-sparsity fast path --------------
__global__ void __launch_bounds__(1024, 1) scan_kernel() {
    extern __shared__ __align__(16) ull ssm[];
    ull*  buf      = ssm + SC_BUF;
    ull*  sup      = ssm + SC_SUP;
    ull*  flg      = ssm + SC_FLG;
    ull*  sh_keepm = ssm + SC_KM;
    int*  sord     = (int*)(ssm + SC_ORD);

    const int b   = blockIdx.x;
    const int tid = threadIdx.x;
    const ull* rows = g_bits + (size_t)b * N * NW;
    const int* order = g_order + b * N;
    float*     keepf = g_keep  + b * N;

    if (tid < 64) { sup[tid] = 0ull; flg[tid] = g_blkflag[b][tid]; }
    #pragma unroll
    for (int l = 0; l < 4; l++) sord[tid + l * 1024] = order[tid + l * 1024];
    __syncthreads();

    const uint32_t smb = (uint32_t)__cvta_generic_to_shared(ssm);

    for (int wb = 0; wb < 64; wb++) {
        const ull fl = flg[wb];
        if (fl == 0ull) {
            // fast path: empty row-block -> keep = not suppressed, sup unchanged
            if (tid < 64) {
                const ull supw = sup[wb];
                const bool k = ((supw >> tid) & 1ull) == 0ull;
                keepf[sord[wb * 64 + tid]] = k ? 1.0f : 0.0f;
            }
            continue;
        }

        // slow path: load the 64x64-word row-block (32 KB)
        {
            const char* src = (const char*)(rows + (size_t)wb * 64 * NW);
            cp_async16(smb + (uint32_t)tid * 16,          src + tid * 16);
            cp_async16(smb + (uint32_t)(tid + 1024) * 16, src + (tid + 1024) * 16);
            asm volatile("cp.async.commit_group;");
            asm volatile("cp.async.wait_group 0;");
        }
        __syncthreads();

        // phase A (warp 0): intra-block keep chain
        if (tid < 32) {
            const int lane = tid;
            ull supw = sup[wb];
            ull keepm;
            if (((fl >> wb) & 1ull) == 0ull) {
                keepm = ~supw;                      // diag word empty
            } else {
                keepm = 0ull;                       // redundant per-lane chain
                #pragma unroll 8
                for (int i = 0; i < 64; i++) {
                    const ull d = buf[i * 64 + wb];
                    const bool k = ((supw >> i) & 1ull) == 0ull;
                    if (k) { supw |= d; keepm |= 1ull << i; }
                }
            }
            const int t0 = wb * 64 + lane;
            keepf[sord[t0]]      = ((keepm >> lane)        & 1ull) ? 1.0f : 0.0f;
            keepf[sord[t0 + 32]] = ((keepm >> (lane + 32)) & 1ull) ? 1.0f : 0.0f;
            if (lane == 0) sh_keepm[0] = keepm;
        }
        __syncthreads();

        // phase B: sup[w] |= OR of kept rows, flagged words w > wb only
        const ull keepm = sh_keepm[0];
        const int w   = tid & 63;
        const int sub = tid >> 6;                   // 16 groups x 4 rows
        if (w > wb && ((fl >> w) & 1ull)) {
            ull p = 0ull;
            #pragma unroll
            for (int r = 0; r < 4; r++) {
                const int i = sub * 4 + r;
                if ((keepm >> i) & 1ull) p |= buf[i * 64 + w];
            }
            if (p) atomicOr(&sup[w], p);
        }
        __syncthreads();
    }
}

// ---------------- 5. outputs -------------------------------------------------
__global__ void mask_kernel(const float4* __restrict__ tok, float4* __restrict__ out) {
    const int idx = blockIdx.x * blockDim.x + threadIdx.x;
    if (idx >= B * N * (D / 4)) return;
    const float k = g_keep[idx >> 6];
    float4 v = tok[idx];
    v.x *= k; v.y *= k; v.z *= k; v.w *= k;
    out[idx] = v;
}
__global__ void keep_out_kernel(float* __restrict__ out, int count) {
    const int t = blockIdx.x * blockDim.x + threadIdx.x;
    if (t < count) out[t] = g_keep[t];
}

// ---------------- launch -----------------------------------------------------
extern "C" void kernel_launch(void* const* d_in, const int* in_sizes, int n_in,
                              void* d_out, int out_size) {
    const float* tokens = (const float*)d_in[0];
    const float* scores = (const float*)d_in[1];
    float* out = (float*)d_out;

    cudaFuncSetAttribute(sim_bits_kernel,
                         cudaFuncAttributeMaxDynamicSharedMemorySize, SIM_SMEM);
    cudaFuncSetAttribute(scan_kernel,
                         cudaFuncAttributeMaxDynamicSharedMemorySize, SCAN_SMEM);

    { dim3 grid(B, 32); rank_kernel<<<grid, 128>>>(scores); }

    {
        const int warps  = B * N;
        const int blocks = (warps * 32 + 255) / 256;
        norm_gather_kernel<<<blocks, 256>>>(tokens);
    }

    { dim3 grid(NPAIR, B); sim_bits_kernel<<<grid, 256, SIM_SMEM>>>(); }

    scan_kernel<<<B, 1024, SCAN_SMEM>>>();

    {
        const int total4 = B * N * (D / 4);
        mask_kernel<<<(total4 + 255) / 256, 256>>>((const float4*)tokens, (float4*)out);
    }

    const long long bnd = (long long)B * N * D;
    if ((long long)out_size > bnd) {
        int extra = (int)((long long)out_size - bnd);
        if (extra > B * N) extra = B * N;
        keep_out_kernel<<<(extra + 255) / 256, 256>>>(out + bnd, extra);
    }
}

// round 7
// speedup vs baseline: 19.7047x; 1.1473x over previous
#include <cuda_runtime.h>
#include <cuda_bf16.h>
#include <cstdint>

#define B 4
#define N 4096
#define D 256
#define NW 64               // 64-bit words per bit-row
#define NT 32               // 128-token tiles per batch
#define NPAIR 528           // NT*(NT+1)/2 upper-tri tile pairs
#define SIM_THR 0.7f
#define LDKB 272            // smem row stride in BYTES (256 fp8 + 16 pad)

typedef unsigned long long ull;

// ---------------- smem layout for sim kernel (bytes) ------------------------
#define ABUF (128 * LDKB)               // 34816
#define SM_A 0
#define SM_B (ABUF)
#define SM_BITS (2 * ABUF)              // 69632
#define SM_FLAG (SM_BITS + 256 * 8)
#define SIM_SMEM (SM_FLAG + 16)         // ~71.7 KB -> 2 CTAs/SM

// ---------------- smem layout for scan kernel (ull units) -------------------
#define SC_BUF  0
#define SC_SUP  4096
#define SC_FLG  (SC_SUP + 64)
#define SC_KM   (SC_FLG + 64)
#define SC_ANY  (SC_KM + 1)
#define SC_ORD  (SC_ANY + 1)
#define SCAN_SMEM ((SC_ORD + 2048) * 8)   // ~50.3 KB

// ---------------- device scratch (zero-initialized at module load) ----------
__device__ unsigned char g_sorted[(size_t)B * N * D];   // e4m3, sorted by score
__device__ int           g_order[B * N];
__device__ ull           g_bits[(size_t)B * N * NW];
__device__ ull           g_blkflag[B][64];
__device__ float         g_keep[B * N];

// ---------------- 1. rank by counting + flag reset ---------------------------
__global__ void rank_kernel(const float* __restrict__ scores) {
    __shared__ float s[N];
    const int b = blockIdx.x, chunk = blockIdx.y, tid = threadIdx.x;  // 128 thr
    if (chunk == 0 && tid < 64) g_blkflag[b][tid] = 0ull;
    const float* sc = scores + b * N;
    for (int t = tid; t < N; t += 128) s[t] = sc[t];
    __syncthreads();
    const int   idx = chunk * 128 + tid;
    const float si  = s[idx];
    int rank = 0;
    #pragma unroll 8
    for (int j = 0; j < N; j++) {
        const float sj = s[j];
        rank += (sj > si) || (sj == si && j < idx);
    }
    g_order[b * N + rank] = idx;
}

// ---------------- 2. normalize + gather (fp32 -> e4m3) ----------------------
__device__ __forceinline__ uint32_t pack_e4m3_4(float a, float b, float c, float d) {
    uint32_t r;
    asm("{\n\t.reg .b16 lo, hi;\n\t"
        "cvt.rn.satfinite.e4m3x2.f32 lo, %2, %1;\n\t"
        "cvt.rn.satfinite.e4m3x2.f32 hi, %4, %3;\n\t"
        "mov.b32 %0, {lo, hi};\n\t}"
        : "=r"(r) : "f"(a), "f"(b), "f"(c), "f"(d));
    return r;
}
__global__ void norm_gather_kernel(const float* __restrict__ tokens) {
    const int gw   = (blockIdx.x * blockDim.x + threadIdx.x) >> 5;
    const int lane = threadIdx.x & 31;
    if (gw >= B * N) return;
    const int src_i = g_order[gw];
    const int b     = gw / N;
    const float* src = tokens + ((size_t)b * N + src_i) * D;
    float4 v0 = *(const float4*)(src + lane * 8);
    float4 v1 = *(const float4*)(src + lane * 8 + 4);
    float ss = v0.x*v0.x + v0.y*v0.y + v0.z*v0.z + v0.w*v0.w
             + v1.x*v1.x + v1.y*v1.y + v1.z*v1.z + v1.w*v1.w;
    #pragma unroll
    for (int o = 16; o > 0; o >>= 1) ss += __shfl_xor_sync(0xffffffffu, ss, o);
    const float inv = 1.0f / (sqrtf(ss) + 1e-6f);
    uint2 u;
    u.x = pack_e4m3_4(v0.x * inv, v0.y * inv, v0.z * inv, v0.w * inv);
    u.y = pack_e4m3_4(v1.x * inv, v1.y * inv, v1.z * inv, v1.w * inv);
    *(uint2*)(g_sorted + (size_t)gw * D + lane * 8) = u;
}

// ---------------- 3. FP8 QMMA similarity: 128x128 tiles -> bits + flags -----
__device__ __forceinline__ void cp_async16(uint32_t saddr, const void* gaddr) {
    asm volatile("cp.async.cg.shared.global [%0], [%1], 16;"
                 :: "r"(saddr), "l"(gaddr));
}
__device__ __forceinline__ void ldm_x4(uint32_t& r0, uint32_t& r1,
                                       uint32_t& r2, uint32_t& r3, uint32_t addr) {
    asm volatile("ldmatrix.sync.aligned.m8n8.x4.shared.b16 {%0,%1,%2,%3}, [%4];"
                 : "=r"(r0), "=r"(r1), "=r"(r2), "=r"(r3) : "r"(addr));
}
__device__ __forceinline__ void qmma16832(float c[4], uint32_t a0, uint32_t a1,
                                          uint32_t a2, uint32_t a3,
                                          uint32_t b0, uint32_t b1) {
    asm volatile("mma.sync.aligned.m16n8k32.row.col.f32.e4m3.e4m3.f32 "
                 "{%0,%1,%2,%3}, {%4,%5,%6,%7}, {%8,%9}, {%0,%1,%2,%3};"
                 : "+f"(c[0]), "+f"(c[1]), "+f"(c[2]), "+f"(c[3])
                 : "r"(a0), "r"(a1), "r"(a2), "r"(a3), "r"(b0), "r"(b1));
}

__global__ void __launch_bounds__(256, 2) sim_bits_kernel() {
    int rem = blockIdx.x, ti = 0;
    while (rem >= NT - ti) { rem -= NT - ti; ti++; }
    const int tj = ti + rem;
    const int b  = blockIdx.y;

    extern __shared__ __align__(128) char sm[];
    const uint32_t smb = (uint32_t)__cvta_generic_to_shared(sm);
    ull*          sbits = (ull*)(sm + SM_BITS);
    unsigned int* sflag = (unsigned int*)(sm + SM_FLAG);

    const int tid = threadIdx.x, lane = tid & 31, wid = tid >> 5;
    const int wm = wid & 1, wn = wid >> 1;   // warp = m64 x n32

    const unsigned char* Ab = g_sorted + ((size_t)b * N + ti * 128) * D;
    const unsigned char* Bb = g_sorted + ((size_t)b * N + tj * 128) * D;

    // stage both tiles (128 rows x 256 fp8 each): 4096 16B chunks, 16/thread
    #pragma unroll
    for (int l = 0; l < 8; l++) {
        const int e   = tid + l * 256;       // 2048 chunks per tile
        const int row = e >> 4;
        const int cb  = (e & 15) * 16;       // byte col
        const uint32_t so = (uint32_t)(row * LDKB + cb);
        cp_async16(smb + SM_A + so, Ab + row * D + cb);
        cp_async16(smb + SM_B + so, Bb + row * D + cb);
    }
    asm volatile("cp.async.commit_group;");

    sbits[tid] = 0ull;
    if (tid < 4) sflag[tid] = 0u;

    float acc[4][4][4] = {};

    asm volatile("cp.async.wait_group 0;");
    __syncthreads();

    // 8 k-steps of 32 fp8 (= 16 b16 cols in the b16-reinterpret view, LDK_b16=136)
    #pragma unroll
    for (int ks = 0; ks < 8; ks++) {
        uint32_t a[4][4];
        #pragma unroll
        for (int tm = 0; tm < 4; tm++) {
            const int row = wm * 64 + tm * 16 + (lane & 15);
            const int col = ks * 16 + ((lane >> 4) << 3);      // b16 units
            ldm_x4(a[tm][0], a[tm][1], a[tm][2], a[tm][3],
                   smb + SM_A + (uint32_t)(row * LDKB + col * 2));
        }
        #pragma unroll
        for (int p = 0; p < 2; p++) {
            const int row = wn * 32 + p * 16 + (lane & 7) + ((lane >> 4) << 3);
            const int col = ks * 16 + (((lane >> 3) & 1) << 3); // b16 units
            uint32_t b0, b1, b2, b3;
            ldm_x4(b0, b1, b2, b3, smb + SM_B + (uint32_t)(row * LDKB + col * 2));
            // (b0,b1): n8 rows p*16+0..7 full k32; (b2,b3): rows p*16+8..15
            #pragma unroll
            for (int tm = 0; tm < 4; tm++) {
                qmma16832(acc[tm][p*2],   a[tm][0], a[tm][1], a[tm][2], a[tm][3], b0, b1);
                qmma16832(acc[tm][p*2+1], a[tm][0], a[tm][1], a[tm][2], a[tm][3], b2, b3);
            }
        }
    }

    const int word = wn >> 1;
    #pragma unroll
    for (int tm = 0; tm < 4; tm++) {
        const int r0  = wm * 64 + tm * 16 + (lane >> 2);
        const int r1  = r0 + 8;
        const int gi0 = ti * 128 + r0;
        const int gi1 = ti * 128 + r1;
        ull m0 = 0ull, m1 = 0ull;
        #pragma unroll
        for (int nt = 0; nt < 4; nt++) {
            const int lc = wn * 32 + nt * 8 + ((lane & 3) << 1);
            const int gj = tj * 128 + lc;
            const int bp = lc & 63;
            if (acc[tm][nt][0] > SIM_THR && gj     > gi0) m0 |= 1ull << bp;
            if (acc[tm][nt][1] > SIM_THR && gj + 1 > gi0) m0 |= 1ull << (bp + 1);
            if (acc[tm][nt][2] > SIM_THR && gj     > gi1) m1 |= 1ull << bp;
            if (acc[tm][nt][3] > SIM_THR && gj + 1 > gi1) m1 |= 1ull << (bp + 1);
        }
        if (m0) atomicOr(&sbits[r0 * 2 + word], m0);
        if (m1) atomicOr(&sbits[r1 * 2 + word], m1);
    }
    __syncthreads();

    const int row = tid >> 1, w = tid & 1;
    const ull myword = sbits[tid];
    g_bits[((size_t)(b * N + ti * 128 + row)) * NW + tj * 2 + w] = myword;

    if (myword) atomicOr(&sflag[((row >> 6) << 1) | w], 1u);
    __syncthreads();
    if (tid < 4 && sflag[tid]) {
        const int rb = ti * 2 + (tid >> 1);
        const int wg = tj * 2 + (tid & 1);
        atomicOr(&g_blkflag[b][rb], 1ull << wg);
    }
}

// ---------------- 4. greedy scan with block-sparsity fast paths -------------
__global__ void __launch_bounds__(1024, 1) scan_kernel() {
    extern __shared__ __align__(16) ull ssm[];
    ull*  buf      = ssm + SC_BUF;
    ull*  sup      = ssm + SC_SUP;
    ull*  flg      = ssm + SC_FLG;
    ull*  sh_keepm = ssm + SC_KM;
    ull*  sh_any   = ssm + SC_ANY;
    int*  sord     = (int*)(ssm + SC_ORD);

    const int b   = blockIdx.x;
    const int tid = threadIdx.x;
    const ull* rows = g_bits + (size_t)b * N * NW;
    const int* order = g_order + b * N;
    float*     keepf = g_keep  + b * N;

    if (tid == 0) sh_any[0] = 0ull;
    if (tid < 64) { sup[tid] = 0ull; flg[tid] = g_blkflag[b][tid]; }
    #pragma unroll
    for (int l = 0; l < 4; l++) sord[tid + l * 1024] = order[tid + l * 1024];
    __syncthreads();
    if (tid < 64 && flg[tid]) atomicOr(sh_any, 1ull);
    __syncthreads();

    if (sh_any[0] == 0ull) {               // nothing suppresses anything
        #pragma unroll
        for (int l = 0; l < 4; l++) keepf[sord[tid + l * 1024]] = 1.0f;
        return;
    }

    const uint32_t smb = (uint32_t)__cvta_generic_to_shared(ssm);

    for (int wb = 0; wb < 64; wb++) {
        const ull fl = flg[wb];
        if (fl == 0ull) {
            if (tid < 64) {
                const ull supw = sup[wb];
                keepf[sord[wb * 64 + tid]] =
                    (((supw >> tid) & 1ull) == 0ull) ? 1.0f : 0.0f;
            }
            continue;
        }

        {
            const char* src = (const char*)(rows + (size_t)wb * 64 * NW);
            cp_async16(smb + (uint32_t)tid * 16,          src + tid * 16);
            cp_async16(smb + (uint32_t)(tid + 1024) * 16, src + (tid + 1024) * 16);
            asm volatile("cp.async.commit_group;");
            asm volatile("cp.async.wait_group 0;");
        }
        __syncthreads();

        if (tid < 32) {
            const int lane = tid;
            ull supw = sup[wb];
            ull keepm;
            if (((fl >> wb) & 1ull) == 0ull) {
                keepm = ~supw;
            } else {
                keepm = 0ull;
                #pragma unroll 8
                for (int i = 0; i < 64; i++) {
                    const ull d = buf[i * 64 + wb];
                    const bool k = ((supw >> i) & 1ull) == 0ull;
                    if (k) { supw |= d; keepm |= 1ull << i; }
                }
            }
            const int t0 = wb * 64 + lane;
            keepf[sord[t0]]      = ((keepm >> lane)        & 1ull) ? 1.0f : 0.0f;
            keepf[sord[t0 + 32]] = ((keepm >> (lane + 32)) & 1ull) ? 1.0f : 0.0f;
            if (lane == 0) sh_keepm[0] = keepm;
        }
        __syncthreads();

        const ull keepm = sh_keepm[0];
        const int w   = tid & 63;
        const int sub = tid >> 6;
        if (w > wb && ((fl >> w) & 1ull)) {
            ull p = 0ull;
            #pragma unroll
            for (int r = 0; r < 4; r++) {
                const int i = sub * 4 + r;
                if ((keepm >> i) & 1ull) p |= buf[i * 64 + w];
            }
            if (p) atomicOr(&sup[w], p);
        }
        __syncthreads();
    }
}

// ---------------- 5. outputs -------------------------------------------------
__global__ void mask_kernel(const float4* __restrict__ tok, float4* __restrict__ out) {
    const int idx = blockIdx.x * blockDim.x + threadIdx.x;
    if (idx >= B * N * (D / 4)) return;
    const float k = g_keep[idx >> 6];
    float4 v = tok[idx];
    v.x *= k; v.y *= k; v.z *= k; v.w *= k;
    out[idx] = v;
}
__global__ void keep_out_kernel(float* __restrict__ out, int count) {
    const int t = blockIdx.x * blockDim.x + threadIdx.x;
    if (t < count) out[t] = g_keep[t];
}

// ---------------- launch -----------------------------------------------------
extern "C" void kernel_launch(void* const* d_in, const int* in_sizes, int n_in,
                              void* d_out, int out_size) {
    const float* tokens = (const float*)d_in[0];
    const float* scores = (const float*)d_in[1];
    float* out = (float*)d_out;

    cudaFuncSetAttribute(sim_bits_kernel,
                         cudaFuncAttributeMaxDynamicSharedMemorySize, SIM_SMEM);
    cudaFuncSetAttribute(scan_kernel,
                         cudaFuncAttributeMaxDynamicSharedMemorySize, SCAN_SMEM);

    { dim3 grid(B, 32); rank_kernel<<<grid, 128>>>(scores); }

    {
        const int warps  = B * N;
        const int blocks = (warps * 32 + 255) / 256;
        norm_gather_kernel<<<blocks, 256>>>(tokens);
    }

    { dim3 grid(NPAIR, B); sim_bits_kernel<<<grid, 256, SIM_SMEM>>>(); }

    scan_kernel<<<B, 1024, SCAN_SMEM>>>();

    {
        const int total4 = B * N * (D / 4);
        mask_kernel<<<(total4 + 255) / 256, 256>>>((const float4*)tokens, (float4*)out);
    }

    const long long bnd = (long long)B * N * D;
    if ((long long)out_size > bnd) {
        int extra = (int)((long long)out_size - bnd);
        if (extra > B * N) extra = B * N;
        keep_out_kernel<<<(extra + 255) / 256, 256>>>(out + bnd, extra);
    }
}

// round 8
// speedup vs baseline: 21.7991x; 1.1063x over previous
#include <cuda_runtime.h>
#include <cuda_bf16.h>
#include <cstdint>

#define B 4
#define N 4096
#define D 256
#define NW 64               // 64-bit words per bit-row
#define NT 32               // 128-token tiles per batch
#define NPAIR 528           // NT*(NT+1)/2 upper-tri tile pairs
#define SIM_THR 0.7f
#define LDKB 272            // smem row stride in BYTES (256 fp8 + 16 pad)

typedef unsigned long long ull;

// ---------------- smem layout for sim kernel (bytes) ------------------------
#define ABUF (128 * LDKB)               // 34816
#define SM_A 0
#define SM_B (ABUF)
#define SM_BITS (2 * ABUF)              // 69632
#define SM_FLAG (SM_BITS + 256 * 8)
#define SIM_SMEM (SM_FLAG + 16)         // ~71.7 KB -> 2 CTAs/SM

// ---------------- smem layout for scan kernel (ull units) -------------------
#define SC_BUF  0
#define SC_SUP  4096
#define SC_FLG  (SC_SUP + 64)
#define SC_KM   (SC_FLG + 64)
#define SC_ANY  (SC_KM + 1)
#define SCAN_SMEM ((SC_ANY + 1) * 8)

// ---------------- device scratch (zero-initialized at module load) ----------
__device__ unsigned char g_sorted[(size_t)B * N * D];   // e4m3, sorted by score
__device__ int           g_order[B * N];                // rank -> original idx
__device__ int           g_invrank[B * N];              // original idx -> rank
__device__ ull           g_bits[(size_t)B * N * NW];
__device__ ull           g_blkflag[B][64];
__device__ ull           g_keepbits[B][64];             // bit i of word w: keep rank w*64+i

// ---------------- 1. rank by counting + flag reset ---------------------------
__global__ void rank_kernel(const float* __restrict__ scores) {
    __shared__ __align__(16) float s[N];
    const int b = blockIdx.x, chunk = blockIdx.y, tid = threadIdx.x;  // 128 thr
    if (chunk == 0 && tid < 64) g_blkflag[b][tid] = 0ull;
    const float* sc = scores + b * N;
    for (int t = tid; t < N; t += 128) s[t] = sc[t];
    __syncthreads();
    const int   idx = chunk * 128 + tid;
    const float si  = s[idx];
    const float4* s4 = (const float4*)s;
    int rank = 0;
    #pragma unroll 4
    for (int j4 = 0; j4 < N / 4; j4++) {
        const float4 v = s4[j4];
        const int j = j4 * 4;
        rank += (v.x > si) || (v.x == si && j     < idx);
        rank += (v.y > si) || (v.y == si && j + 1 < idx);
        rank += (v.z > si) || (v.z == si && j + 2 < idx);
        rank += (v.w > si) || (v.w == si && j + 3 < idx);
    }
    g_order[b * N + rank]  = idx;
    g_invrank[b * N + idx] = rank;
}

// ---------------- 2. normalize + gather (fp32 -> e4m3) ----------------------
__device__ __forceinline__ uint32_t pack_e4m3_4(float a, float b, float c, float d) {
    uint32_t r;
    asm("{\n\t.reg .b16 lo, hi;\n\t"
        "cvt.rn.satfinite.e4m3x2.f32 lo, %2, %1;\n\t"
        "cvt.rn.satfinite.e4m3x2.f32 hi, %4, %3;\n\t"
        "mov.b32 %0, {lo, hi};\n\t}"
        : "=r"(r) : "f"(a), "f"(b), "f"(c), "f"(d));
    return r;
}
__global__ void norm_gather_kernel(const float* __restrict__ tokens) {
    const int gw   = (blockIdx.x * blockDim.x + threadIdx.x) >> 5;
    const int lane = threadIdx.x & 31;
    if (gw >= B * N) return;
    const int src_i = g_order[gw];
    const int b     = gw / N;
    const float* src = tokens + ((size_t)b * N + src_i) * D;
    float4 v0 = *(const float4*)(src + lane * 8);
    float4 v1 = *(const float4*)(src + lane * 8 + 4);
    float ss = v0.x*v0.x + v0.y*v0.y + v0.z*v0.z + v0.w*v0.w
             + v1.x*v1.x + v1.y*v1.y + v1.z*v1.z + v1.w*v1.w;
    #pragma unroll
    for (int o = 16; o > 0; o >>= 1) ss += __shfl_xor_sync(0xffffffffu, ss, o);
    const float inv = 1.0f / (sqrtf(ss) + 1e-6f);
    uint2 u;
    u.x = pack_e4m3_4(v0.x * inv, v0.y * inv, v0.z * inv, v0.w * inv);
    u.y = pack_e4m3_4(v1.x * inv, v1.y * inv, v1.z * inv, v1.w * inv);
    *(uint2*)(g_sorted + (size_t)gw * D + lane * 8) = u;
}

// ---------------- 3. FP8 QMMA similarity: 128x128 tiles -> bits + flags -----
__device__ __forceinline__ void cp_async16(uint32_t saddr, const void* gaddr) {
    asm volatile("cp.async.cg.shared.global [%0], [%1], 16;"
                 :: "r"(saddr), "l"(gaddr));
}
__device__ __forceinline__ void ldm_x4(uint32_t& r0, uint32_t& r1,
                                       uint32_t& r2, uint32_t& r3, uint32_t addr) {
    asm volatile("ldmatrix.sync.aligned.m8n8.x4.shared.b16 {%0,%1,%2,%3}, [%4];"
                 : "=r"(r0), "=r"(r1), "=r"(r2), "=r"(r3) : "r"(addr));
}
__device__ __forceinline__ void qmma16832(float c[4], uint32_t a0, uint32_t a1,
                                          uint32_t a2, uint32_t a3,
                                          uint32_t b0, uint32_t b1) {
    asm volatile("mma.sync.aligned.m16n8k32.row.col.f32.e4m3.e4m3.f32 "
                 "{%0,%1,%2,%3}, {%4,%5,%6,%7}, {%8,%9}, {%0,%1,%2,%3};"
                 : "+f"(c[0]), "+f"(c[1]), "+f"(c[2]), "+f"(c[3])
                 : "r"(a0), "r"(a1), "r"(a2), "r"(a3), "r"(b0), "r"(b1));
}

__global__ void __launch_bounds__(256, 2) sim_bits_kernel() {
    int rem = blockIdx.x, ti = 0;
    while (rem >= NT - ti) { rem -= NT - ti; ti++; }
    const int tj = ti + rem;
    const int b  = blockIdx.y;

    extern __shared__ __align__(128) char sm[];
    const uint32_t smb = (uint32_t)__cvta_generic_to_shared(sm);
    ull*          sbits = (ull*)(sm + SM_BITS);
    unsigned int* sflag = (unsigned int*)(sm + SM_FLAG);

    const int tid = threadIdx.x, lane = tid & 31, wid = tid >> 5;
    const int wm = wid & 1, wn = wid >> 1;   // warp = m64 x n32

    const unsigned char* Ab = g_sorted + ((size_t)b * N + ti * 128) * D;
    const unsigned char* Bb = g_sorted + ((size_t)b * N + tj * 128) * D;

    #pragma unroll
    for (int l = 0; l < 8; l++) {
        const int e   = tid + l * 256;
        const int row = e >> 4;
        const int cb  = (e & 15) * 16;
        const uint32_t so = (uint32_t)(row * LDKB + cb);
        cp_async16(smb + SM_A + so, Ab + row * D + cb);
        cp_async16(smb + SM_B + so, Bb + row * D + cb);
    }
    asm volatile("cp.async.commit_group;");

    sbits[tid] = 0ull;
    if (tid < 4) sflag[tid] = 0u;

    float acc[4][4][4] = {};

    asm volatile("cp.async.wait_group 0;");
    __syncthreads();

    #pragma unroll
    for (int ks = 0; ks < 8; ks++) {
        uint32_t a[4][4];
        #pragma unroll
        for (int tm = 0; tm < 4; tm++) {
            const int row = wm * 64 + tm * 16 + (lane & 15);
            const int col = ks * 16 + ((lane >> 4) << 3);      // b16 units
            ldm_x4(a[tm][0], a[tm][1], a[tm][2], a[tm][3],
                   smb + SM_A + (uint32_t)(row * LDKB + col * 2));
        }
        #pragma unroll
        for (int p = 0; p < 2; p++) {
            const int row = wn * 32 + p * 16 + (lane & 7) + ((lane >> 4) << 3);
            const int col = ks * 16 + (((lane >> 3) & 1) << 3);
            uint32_t b0, b1, b2, b3;
            ldm_x4(b0, b1, b2, b3, smb + SM_B + (uint32_t)(row * LDKB + col * 2));
            #pragma unroll
            for (int tm = 0; tm < 4; tm++) {
                qmma16832(acc[tm][p*2],   a[tm][0], a[tm][1], a[tm][2], a[tm][3], b0, b1);
                qmma16832(acc[tm][p*2+1], a[tm][0], a[tm][1], a[tm][2], a[tm][3], b2, b3);
            }
        }
    }

    const int word = wn >> 1;
    #pragma unroll
    for (int tm = 0; tm < 4; tm++) {
        const int r0  = wm * 64 + tm * 16 + (lane >> 2);
        const int r1  = r0 + 8;
        const int gi0 = ti * 128 + r0;
        const int gi1 = ti * 128 + r1;
        ull m0 = 0ull, m1 = 0ull;
        #pragma unroll
        for (int nt = 0; nt < 4; nt++) {
            const int lc = wn * 32 + nt * 8 + ((lane & 3) << 1);
            const int gj = tj * 128 + lc;
            const int bp = lc & 63;
            if (acc[tm][nt][0] > SIM_THR && gj     > gi0) m0 |= 1ull << bp;
            if (acc[tm][nt][1] > SIM_THR && gj + 1 > gi0) m0 |= 1ull << (bp + 1);
            if (acc[tm][nt][2] > SIM_THR && gj     > gi1) m1 |= 1ull << bp;
            if (acc[tm][nt][3] > SIM_THR && gj + 1 > gi1) m1 |= 1ull << (bp + 1);
        }
        if (m0) atomicOr(&sbits[r0 * 2 + word], m0);
        if (m1) atomicOr(&sbits[r1 * 2 + word], m1);
    }
    __syncthreads();

    const int row = tid >> 1, w = tid & 1;
    const ull myword = sbits[tid];
    g_bits[((size_t)(b * N + ti * 128 + row)) * NW + tj * 2 + w] = myword;

    if (myword) atomicOr(&sflag[((row >> 6) << 1) | w], 1u);
    __syncthreads();
    if (tid < 4 && sflag[tid]) {
        const int rb = ti * 2 + (tid >> 1);
        const int wg = tj * 2 + (tid & 1);
        atomicOr(&g_blkflag[b][rb], 1ull << wg);
    }
}

// ---------------- 4. greedy scan -> keep bitmask (sorted order) -------------
__global__ void __launch_bounds__(1024, 1) scan_kernel() {
    extern __shared__ __align__(16) ull ssm[];
    ull*  buf      = ssm + SC_BUF;
    ull*  sup      = ssm + SC_SUP;
    ull*  flg      = ssm + SC_FLG;
    ull*  sh_keepm = ssm + SC_KM;
    ull*  sh_any   = ssm + SC_ANY;

    const int b   = blockIdx.x;
    const int tid = threadIdx.x;
    const ull* rows = g_bits + (size_t)b * N * NW;

    if (tid == 0) sh_any[0] = 0ull;
    if (tid < 64) { sup[tid] = 0ull; flg[tid] = g_blkflag[b][tid]; }
    __syncthreads();
    if (tid < 64 && flg[tid]) atomicOr(sh_any, 1ull);
    __syncthreads();

    if (sh_any[0] == 0ull) {               // nothing suppresses anything
        if (tid < 64) g_keepbits[b][tid] = ~0ull;
        return;
    }

    const uint32_t smb = (uint32_t)__cvta_generic_to_shared(ssm);

    for (int wb = 0; wb < 64; wb++) {
        const ull fl = flg[wb];
        if (fl == 0ull) {
            if (tid == 0) g_keepbits[b][wb] = ~sup[wb];
            continue;
        }

        {
            const char* src = (const char*)(rows + (size_t)wb * 64 * NW);
            cp_async16(smb + (uint32_t)tid * 16,          src + tid * 16);
            cp_async16(smb + (uint32_t)(tid + 1024) * 16, src + (tid + 1024) * 16);
            asm volatile("cp.async.commit_group;");
            asm volatile("cp.async.wait_group 0;");
        }
        __syncthreads();

        if (tid < 32) {
            ull supw = sup[wb];
            ull keepm;
            if (((fl >> wb) & 1ull) == 0ull) {
                keepm = ~supw;
            } else {
                keepm = 0ull;                       // redundant per-lane chain
                #pragma unroll 8
                for (int i = 0; i < 64; i++) {
                    const ull d = buf[i * 64 + wb];
                    const bool k = ((supw >> i) & 1ull) == 0ull;
                    if (k) { supw |= d; keepm |= 1ull << i; }
                }
            }
            if (tid == 0) { sh_keepm[0] = keepm; g_keepbits[b][wb] = keepm; }
        }
        __syncthreads();

        const ull keepm = sh_keepm[0];
        const int w   = tid & 63;
        const int sub = tid >> 6;
        if (w > wb && ((fl >> w) & 1ull)) {
            ull p = 0ull;
            #pragma unroll
            for (int r = 0; r < 4; r++) {
                const int i = sub * 4 + r;
                if ((keepm >> i) & 1ull) p |= buf[i * 64 + w];
            }
            if (p) atomicOr(&sup[w], p);
        }
        __syncthreads();
    }
}

// ---------------- 5. masked tokens + keep tail in one kernel ----------------
__global__ void mask_kernel(const float4* __restrict__ tok, float* __restrict__ out,
                            int tail_count) {
    const int idx = blockIdx.x * blockDim.x + threadIdx.x;
    const int total4 = B * N * (D / 4);
    if (idx < total4) {
        const int token = idx >> 6;                // D/4 = 64 float4 per token
        const int b     = token >> 12;             // N = 4096
        const int r     = g_invrank[token];
        const float k   = ((g_keepbits[b][r >> 6] >> (r & 63)) & 1ull) ? 1.0f : 0.0f;
        float4 v = tok[idx];
        v.x *= k; v.y *= k; v.z *= k; v.w *= k;
        ((float4*)out)[idx] = v;
    } else {
        const int t = idx - total4;                // tail: keep floats, original order
        if (t < tail_count) {
            const int b = t >> 12;
            const int r = g_invrank[t];
            out[(size_t)B * N * D + t] =
                ((g_keepbits[b][r >> 6] >> (r & 63)) & 1ull) ? 1.0f : 0.0f;
        }
    }
}

// ---------------- launch -----------------------------------------------------
extern "C" void kernel_launch(void* const* d_in, const int* in_sizes, int n_in,
                              void* d_out, int out_size) {
    const float* tokens = (const float*)d_in[0];
    const float* scores = (const float*)d_in[1];
    float* out = (float*)d_out;

    cudaFuncSetAttribute(sim_bits_kernel,
                         cudaFuncAttributeMaxDynamicSharedMemorySize, SIM_SMEM);
    cudaFuncSetAttribute(scan_kernel,
                         cudaFuncAttributeMaxDynamicSharedMemorySize, SCAN_SMEM);

    { dim3 grid(B, 32); rank_kernel<<<grid, 128>>>(scores); }

    {
        const int warps  = B * N;
        const int blocks = (warps * 32 + 255) / 256;
        norm_gather_kernel<<<blocks, 256>>>(tokens);
    }

    { dim3 grid(NPAIR, B); sim_bits_kernel<<<grid, 256, SIM_SMEM>>>(); }

    scan_kernel<<<B, 1024, SCAN_SMEM>>>();

    {
        const long long bnd = (long long)B * N * D;
        int tail = 0;
        if ((long long)out_size > bnd) {
            tail = (int)((long long)out_size - bnd);
            if (tail > B * N) tail = B * N;
        }
        const int total = B * N * (D / 4) + tail;
        mask_kernel<<<(total + 255) / 256, 256>>>((const float4*)tokens, out, tail);
    }
}

// round 9
// speedup vs baseline: 22.7809x; 1.0450x over previous
#include <cuda_runtime.h>
#include <cuda_bf16.h>
#include <cuda_fp16.h>
#include <cstdint>

#define B 4
#define N 4096
#define D 256
#define NW 64               // 64-bit words per bit-row
#define NT 32               // 128-token tiles per batch
#define NPAIR 528           // NT*(NT+1)/2 upper-tri tile pairs
#define SIM_THR 0.7f
#define LDKB 272            // smem row stride in BYTES (256 fp8 + 16 pad)

typedef unsigned long long ull;

// ---------------- smem layout for sim kernel (bytes) ------------------------
#define ABUF (128 * LDKB)               // 34816
#define SM_A 0
#define SM_B (ABUF)
#define SM_BITS (2 * ABUF)              // 69632
#define SM_FLAG (SM_BITS + 256 * 8)
#define SIM_SMEM (SM_FLAG + 16)         // ~71.7 KB -> 2 CTAs/SM

// ---------------- smem layout for scan kernel (ull units) -------------------
#define SC_BUF  0
#define SC_SUP  4096
#define SC_FLG  (SC_SUP + 64)
#define SC_KM   (SC_FLG + 64)
#define SC_ANY  (SC_KM + 1)
#define SCAN_SMEM ((SC_ANY + 1) * 8)

// ---------------- device scratch (zero-initialized at module load) ----------
__device__ unsigned char g_sorted[(size_t)B * N * D];   // e4m3, sorted by score
__device__ int           g_order[B * N];                // rank -> original idx
__device__ int           g_invrank[B * N];              // original idx -> rank
__device__ ull           g_bits[(size_t)B * N * NW];
__device__ ull           g_blkflag[B][64];
__device__ ull           g_keepbits[B][64];             // bit i of word w: keep rank w*64+i

// ---------------- 1. rank by counting + flag reset ---------------------------
__global__ void rank_kernel(const float* __restrict__ scores) {
    __shared__ __align__(16) float s[N];
    const int b = blockIdx.x, chunk = blockIdx.y, tid = threadIdx.x;  // 128 thr
    if (chunk == 0 && tid < 64) g_blkflag[b][tid] = 0ull;
    const float* sc = scores + b * N;
    for (int t = tid; t < N; t += 128) s[t] = sc[t];
    __syncthreads();
    const int   idx = chunk * 128 + tid;
    const float si  = s[idx];
    const float4* s4 = (const float4*)s;
    int rank = 0;
    #pragma unroll 4
    for (int j4 = 0; j4 < N / 4; j4++) {
        const float4 v = s4[j4];
        const int j = j4 * 4;
        rank += (v.x > si) || (v.x == si && j     < idx);
        rank += (v.y > si) || (v.y == si && j + 1 < idx);
        rank += (v.z > si) || (v.z == si && j + 2 < idx);
        rank += (v.w > si) || (v.w == si && j + 3 < idx);
    }
    g_order[b * N + rank]  = idx;
    g_invrank[b * N + idx] = rank;
}

// ---------------- 2. normalize + gather (fp32 -> e4m3) ----------------------
__device__ __forceinline__ uint32_t pack_e4m3_4(float a, float b, float c, float d) {
    uint32_t r;
    asm("{\n\t.reg .b16 lo, hi;\n\t"
        "cvt.rn.satfinite.e4m3x2.f32 lo, %2, %1;\n\t"
        "cvt.rn.satfinite.e4m3x2.f32 hi, %4, %3;\n\t"
        "mov.b32 %0, {lo, hi};\n\t}"
        : "=r"(r) : "f"(a), "f"(b), "f"(c), "f"(d));
    return r;
}
__global__ void norm_gather_kernel(const float* __restrict__ tokens) {
    const int gw   = (blockIdx.x * blockDim.x + threadIdx.x) >> 5;
    const int lane = threadIdx.x & 31;
    if (gw >= B * N) return;
    const int src_i = g_order[gw];
    const int b     = gw / N;
    const float* src = tokens + ((size_t)b * N + src_i) * D;
    float4 v0 = *(const float4*)(src + lane * 8);
    float4 v1 = *(const float4*)(src + lane * 8 + 4);
    float ss = v0.x*v0.x + v0.y*v0.y + v0.z*v0.z + v0.w*v0.w
             + v1.x*v1.x + v1.y*v1.y + v1.z*v1.z + v1.w*v1.w;
    #pragma unroll
    for (int o = 16; o > 0; o >>= 1) ss += __shfl_xor_sync(0xffffffffu, ss, o);
    const float inv = 1.0f / (sqrtf(ss) + 1e-6f);
    uint2 u;
    u.x = pack_e4m3_4(v0.x * inv, v0.y * inv, v0.z * inv, v0.w * inv);
    u.y = pack_e4m3_4(v1.x * inv, v1.y * inv, v1.z * inv, v1.w * inv);
    *(uint2*)(g_sorted + (size_t)gw * D + lane * 8) = u;
}

// ---------------- 3. FP8 QMMA (f16 accum): 128x128 tiles -> bits + flags ----
__device__ __forceinline__ void cp_async16(uint32_t saddr, const void* gaddr) {
    asm volatile("cp.async.cg.shared.global [%0], [%1], 16;"
                 :: "r"(saddr), "l"(gaddr));
}
__device__ __forceinline__ void ldm_x4(uint32_t& r0, uint32_t& r1,
                                       uint32_t& r2, uint32_t& r3, uint32_t addr) {
    asm volatile("ldmatrix.sync.aligned.m8n8.x4.shared.b16 {%0,%1,%2,%3}, [%4];"
                 : "=r"(r0), "=r"(r1), "=r"(r2), "=r"(r3) : "r"(addr));
}
__device__ __forceinline__ void qmma16832_h(uint32_t c[2], uint32_t a0, uint32_t a1,
                                            uint32_t a2, uint32_t a3,
                                            uint32_t b0, uint32_t b1) {
    asm volatile("mma.sync.aligned.m16n8k32.row.col.f16.e4m3.e4m3.f16 "
                 "{%0,%1}, {%2,%3,%4,%5}, {%6,%7}, {%0,%1};"
                 : "+r"(c[0]), "+r"(c[1])
                 : "r"(a0), "r"(a1), "r"(a2), "r"(a3), "r"(b0), "r"(b1));
}

__global__ void __launch_bounds__(256, 2) sim_bits_kernel() {
    int rem = blockIdx.x, ti = 0;
    while (rem >= NT - ti) { rem -= NT - ti; ti++; }
    const int tj = ti + rem;
    const int b  = blockIdx.y;

    extern __shared__ __align__(128) char sm[];
    const uint32_t smb = (uint32_t)__cvta_generic_to_shared(sm);
    ull*          sbits = (ull*)(sm + SM_BITS);
    unsigned int* sflag = (unsigned int*)(sm + SM_FLAG);

    const int tid = threadIdx.x, lane = tid & 31, wid = tid >> 5;
    const int wm = wid & 1, wn = wid >> 1;   // warp = m64 x n32

    const unsigned char* Ab = g_sorted + ((size_t)b * N + ti * 128) * D;
    const unsigned char* Bb = g_sorted + ((size_t)b * N + tj * 128) * D;

    #pragma unroll
    for (int l = 0; l < 8; l++) {
        const int e   = tid + l * 256;
        const int row = e >> 4;
        const int cb  = (e & 15) * 16;
        const uint32_t so = (uint32_t)(row * LDKB + cb);
        cp_async16(smb + SM_A + so, Ab + row * D + cb);
        cp_async16(smb + SM_B + so, Bb + row * D + cb);
    }
    asm volatile("cp.async.commit_group;");

    sbits[tid] = 0ull;
    if (tid < 4) sflag[tid] = 0u;

    // diagonal tiles: warp regions fully below the diagonal produce no bits
    const bool live = !(ti == tj && (wn * 32 + 32) <= (wm * 64));

    uint32_t acc[4][4][2] = {};     // f16x2 accumulators

    asm volatile("cp.async.wait_group 0;");
    __syncthreads();

    if (live) {
        #pragma unroll
        for (int ks = 0; ks < 8; ks++) {
            uint32_t a[4][4];
            #pragma unroll
            for (int tm = 0; tm < 4; tm++) {
                const int row = wm * 64 + tm * 16 + (lane & 15);
                const int col = ks * 16 + ((lane >> 4) << 3);      // b16 units
                ldm_x4(a[tm][0], a[tm][1], a[tm][2], a[tm][3],
                       smb + SM_A + (uint32_t)(row * LDKB + col * 2));
            }
            #pragma unroll
            for (int p = 0; p < 2; p++) {
                const int row = wn * 32 + p * 16 + (lane & 7) + ((lane >> 4) << 3);
                const int col = ks * 16 + (((lane >> 3) & 1) << 3);
                uint32_t b0, b1, b2, b3;
                ldm_x4(b0, b1, b2, b3, smb + SM_B + (uint32_t)(row * LDKB + col * 2));
                #pragma unroll
                for (int tm = 0; tm < 4; tm++) {
                    qmma16832_h(acc[tm][p*2],   a[tm][0], a[tm][1], a[tm][2], a[tm][3], b0, b1);
                    qmma16832_h(acc[tm][p*2+1], a[tm][0], a[tm][1], a[tm][2], a[tm][3], b2, b3);
                }
            }
        }

        const int word = wn >> 1;
        #pragma unroll
        for (int tm = 0; tm < 4; tm++) {
            const int r0  = wm * 64 + tm * 16 + (lane >> 2);
            const int r1  = r0 + 8;
            const int gi0 = ti * 128 + r0;
            const int gi1 = ti * 128 + r1;
            ull m0 = 0ull, m1 = 0ull;
            #pragma unroll
            for (int nt = 0; nt < 4; nt++) {
                const int lc = wn * 32 + nt * 8 + ((lane & 3) << 1);
                const int gj = tj * 128 + lc;
                const int bp = lc & 63;
                const float2 f0 = __half22float2(*reinterpret_cast<__half2*>(&acc[tm][nt][0]));
                const float2 f1 = __half22float2(*reinterpret_cast<__half2*>(&acc[tm][nt][1]));
                if (f0.x > SIM_THR && gj     > gi0) m0 |= 1ull << bp;
                if (f0.y > SIM_THR && gj + 1 > gi0) m0 |= 1ull << (bp + 1);
                if (f1.x > SIM_THR && gj     > gi1) m1 |= 1ull << bp;
                if (f1.y > SIM_THR && gj + 1 > gi1) m1 |= 1ull << (bp + 1);
            }
            if (m0) atomicOr(&sbits[r0 * 2 + word], m0);
            if (m1) atomicOr(&sbits[r1 * 2 + word], m1);
        }
    }
    __syncthreads();

    const int row = tid >> 1, w = tid & 1;
    const ull myword = sbits[tid];
    g_bits[((size_t)(b * N + ti * 128 + row)) * NW + tj * 2 + w] = myword;

    if (myword) atomicOr(&sflag[((row >> 6) << 1) | w], 1u);
    __syncthreads();
    if (tid < 4 && sflag[tid]) {
        const int rb = ti * 2 + (tid >> 1);
        const int wg = tj * 2 + (tid & 1);
        atomicOr(&g_blkflag[b][rb], 1ull << wg);
    }
}

// ---------------- 4. greedy scan -> keep bitmask (sorted order) -------------
__global__ void __launch_bounds__(1024, 1) scan_kernel() {
    extern __shared__ __align__(16) ull ssm[];
    ull*  buf      = ssm + SC_BUF;
    ull*  sup      = ssm + SC_SUP;
    ull*  flg      = ssm + SC_FLG;
    ull*  sh_keepm = ssm + SC_KM;
    ull*  sh_any   = ssm + SC_ANY;

    const int b   = blockIdx.x;
    const int tid = threadIdx.x;
    const ull* rows = g_bits + (size_t)b * N * NW;

    if (tid == 0) sh_any[0] = 0ull;
    if (tid < 64) { sup[tid] = 0ull; flg[tid] = g_blkflag[b][tid]; }
    __syncthreads();
    if (tid < 64 && flg[tid]) atomicOr(sh_any, 1ull);
    __syncthreads();

    if (sh_any[0] == 0ull) {               // nothing suppresses anything
        if (tid < 64) g_keepbits[b][tid] = ~0ull;
        return;
    }

    const uint32_t smb = (uint32_t)__cvta_generic_to_shared(ssm);

    for (int wb = 0; wb < 64; wb++) {
        const ull fl = flg[wb];
        if (fl == 0ull) {
            if (tid == 0) g_keepbits[b][wb] = ~sup[wb];
            continue;
        }

        {
            const char* src = (const char*)(rows + (size_t)wb * 64 * NW);
            cp_async16(smb + (uint32_t)tid * 16,          src + tid * 16);
            cp_async16(smb + (uint32_t)(tid + 1024) * 16, src + (tid + 1024) * 16);
            asm volatile("cp.async.commit_group;");
            asm volatile("cp.async.wait_group 0;");
        }
        __syncthreads();

        if (tid < 32) {
            ull supw = sup[wb];
            ull keepm;
            if (((fl >> wb) & 1ull) == 0ull) {
                keepm = ~supw;
            } else {
                keepm = 0ull;                       // redundant per-lane chain
                #pragma unroll 8
                for (int i = 0; i < 64; i++) {
                    const ull d = buf[i * 64 + wb];
                    const bool k = ((supw >> i) & 1ull) == 0ull;
                    if (k) { supw |= d; keepm |= 1ull << i; }
                }
            }
            if (tid == 0) { sh_keepm[0] = keepm; g_keepbits[b][wb] = keepm; }
        }
        __syncthreads();

        const ull keepm = sh_keepm[0];
        const int w   = tid & 63;
        const int sub = tid >> 6;
        if (w > wb && ((fl >> w) & 1ull)) {
            ull p = 0ull;
            #pragma unroll
            for (int r = 0; r < 4; r++) {
                const int i = sub * 4 + r;
                if ((keepm >> i) & 1ull) p |= buf[i * 64 + w];
            }
            if (p) atomicOr(&sup[w], p);
        }
        __syncthreads();
    }
}

// ---------------- 5. masked tokens + keep tail in one kernel ----------------
__global__ void mask_kernel(const float4* __restrict__ tok, float* __restrict__ out,
                            int tail_count) {
    const int idx = blockIdx.x * blockDim.x + threadIdx.x;
    const int total4 = B * N * (D / 4);
    if (idx < total4) {
        const int token = idx >> 6;                // D/4 = 64 float4 per token
        const int b     = token >> 12;             // N = 4096
        const int r     = g_invrank[token];
        const float k   = ((g_keepbits[b][r >> 6] >> (r & 63)) & 1ull) ? 1.0f : 0.0f;
        float4 v = tok[idx];
        v.x *= k; v.y *= k; v.z *= k; v.w *= k;
        ((float4*)out)[idx] = v;
    } else {
        const int t = idx - total4;                // tail: keep floats, original order
        if (t < tail_count) {
            const int b = t >> 12;
            const int r = g_invrank[t];
            out[(size_t)B * N * D + t] =
                ((g_keepbits[b][r >> 6] >> (r & 63)) & 1ull) ? 1.0f : 0.0f;
        }
    }
}

// ---------------- launch -----------------------------------------------------
extern "C" void kernel_launch(void* const* d_in, const int* in_sizes, int n_in,
                              void* d_out, int out_size) {
    const float* tokens = (const float*)d_in[0];
    const float* scores = (const float*)d_in[1];
    float* out = (float*)d_out;

    cudaFuncSetAttribute(sim_bits_kernel,
                         cudaFuncAttributeMaxDynamicSharedMemorySize, SIM_SMEM);
    cudaFuncSetAttribute(scan_kernel,
                         cudaFuncAttributeMaxDynamicSharedMemorySize, SCAN_SMEM);

    { dim3 grid(B, 32); rank_kernel<<<grid, 128>>>(scores); }

    {
        const int warps  = B * N;
        const int blocks = (warps * 32 + 255) / 256;
        norm_gather_kernel<<<blocks, 256>>>(tokens);
    }

    { dim3 grid(NPAIR, B); sim_bits_kernel<<<grid, 256, SIM_SMEM>>>(); }

    scan_kernel<<<B, 1024, SCAN_SMEM>>>();

    {
        const long long bnd = (long long)B * N * D;
        int tail = 0;
        if ((long long)out_size > bnd) {
            tail = (int)((long long)out_size - bnd);
            if (tail > B * N) tail = B * N;
        }
        const int total = B * N * (D / 4) + tail;
        mask_kernel<<<(total + 255) / 256, 256>>>((const float4*)tokens, out, tail);
    }
}